// round 1
// baseline (speedup 1.0000x reference)
#include <cuda_runtime.h>

#define NMAX 50000
#define EMAX 800000
#define FDIM 96
#define DEG_PAD 128

// ---------------- scratch (device globals: allocation-free) ----------------
__device__ int   g_deg[NMAX];
__device__ float g_dis[NMAX];
__device__ __align__(16) int   g_ell[(size_t)NMAX * DEG_PAD];
__device__ __align__(16) float g_A [(size_t)NMAX * FDIM];   // P x
__device__ __align__(16) float g_G1[(size_t)NMAX * FDIM];   // relu(A W_g1 + b)
__device__ __align__(16) float g_B [(size_t)NMAX * FDIM];   // P g1
__device__ __align__(16) float g_LG[(size_t)NMAX * 2 * FDIM]; // [local | g2]

// ---------------- degree / ELL build ----------------
__global__ void k_zero(int n) {
    int i = blockIdx.x * blockDim.x + threadIdx.x;
    if (i < n) g_deg[i] = 0;
}

__global__ void k_count(const int* __restrict__ ei, int e_cnt) {
    int e = blockIdx.x * blockDim.x + threadIdx.x;
    if (e < e_cnt) atomicAdd(&g_deg[ei[e_cnt + e]], 1);   // dst row of edge_index
}

__global__ void k_dis(int n) {
    int i = blockIdx.x * blockDim.x + threadIdx.x;
    if (i < n) {
        g_dis[i] = rsqrtf((float)(g_deg[i] + 1));  // +1 self-loop
        g_deg[i] = 0;                              // reuse as fill cursor
    }
}

__global__ void k_fill(const int* __restrict__ ei, int e_cnt) {
    int e = blockIdx.x * blockDim.x + threadIdx.x;
    if (e < e_cnt) {
        int s = ei[e];
        int d = ei[e_cnt + e];
        int p = atomicAdd(&g_deg[d], 1);
        if (p < DEG_PAD) g_ell[(size_t)d * DEG_PAD + p] = s;
    }
}

// ---------------- aggregation: out[i] = dis[i]*( sum_e dis[src] h[src] + dis[i] h[i] )
// one warp per node; 3 coalesced 128B loads per edge; acc in registers
__global__ void __launch_bounds__(256) k_agg(const float* __restrict__ h,
                                             float* __restrict__ out, int n) {
    int warp = blockIdx.x * 8 + (threadIdx.x >> 5);
    int lane = threadIdx.x & 31;
    if (warp >= n) return;

    int cnt = g_deg[warp];
    cnt = cnt < DEG_PAD ? cnt : DEG_PAD;
    float di = g_dis[warp];
    const int* row = g_ell + (size_t)warp * DEG_PAD;

    const float* hs = h + (size_t)warp * FDIM;   // self loop (norm = dis^2)
    float a0 = di * hs[lane];
    float a1 = di * hs[lane + 32];
    float a2 = di * hs[lane + 64];

    for (int base = 0; base < cnt; base += 32) {
        int take = cnt - base; if (take > 32) take = 32;
        int s = 0; float w = 0.f;
        if (lane < take) { s = row[base + lane]; w = g_dis[s]; }
        #pragma unroll 4
        for (int j = 0; j < take; j++) {
            int   ss = __shfl_sync(0xffffffffu, s, j);
            float ww = __shfl_sync(0xffffffffu, w, j);
            const float* hp = h + (size_t)ss * FDIM;
            a0 += ww * hp[lane];
            a1 += ww * hp[lane + 32];
            a2 += ww * hp[lane + 64];
        }
    }
    float* op = out + (size_t)warp * FDIM;
    op[lane]      = di * a0;
    op[lane + 32] = di * a1;
    op[lane + 64] = di * a2;
}

// ---------------- GEMM: C[M x 96] = act( X[M x K] @ W[K x 96] + b )
// BM=64, BN=96, BK=32; 256 threads; 4x6 register micro-tile per thread
#define BM 64
#define BKK 32
#define BN 96

__global__ void __launch_bounds__(256) k_gemm(const float* __restrict__ X, int ldx, int K,
                                              const float* __restrict__ W,
                                              const float* __restrict__ bias,
                                              float* __restrict__ C, int ldc,
                                              int M, int do_relu) {
    __shared__ float Xs[BKK][BM + 1];  // transposed X tile, +1 pad (store conflicts)
    __shared__ float Ws[BKK][BN];

    int t  = threadIdx.x;
    int tx = t & 15;        // col group: cols tx*6 .. tx*6+5
    int ty = t >> 4;        // row group: rows ty*4 .. ty*4+3
    int row0 = blockIdx.x * BM;

    float acc[4][6];
    #pragma unroll
    for (int r = 0; r < 4; r++)
        #pragma unroll
        for (int j = 0; j < 6; j++) acc[r][j] = 0.f;

    for (int k0 = 0; k0 < K; k0 += BKK) {
        // load X tile (64 x 32) as float4, store transposed
        #pragma unroll
        for (int i = 0; i < 2; i++) {
            int idx = t + i * 256;          // 0..511
            int m   = idx >> 3;             // 8 float4 per row
            int kq  = (idx & 7) << 2;
            float4 v = make_float4(0.f, 0.f, 0.f, 0.f);
            int row = row0 + m;
            if (row < M)
                v = *reinterpret_cast<const float4*>(X + (size_t)row * ldx + k0 + kq);
            Xs[kq + 0][m] = v.x; Xs[kq + 1][m] = v.y;
            Xs[kq + 2][m] = v.z; Xs[kq + 3][m] = v.w;
        }
        // load W tile (32 x 96) as float4
        #pragma unroll
        for (int i = 0; i < 3; i++) {
            int idx = t + i * 256;          // 0..767
            int kk  = idx / 24;
            int nq  = (idx % 24) << 2;
            float4 v = *reinterpret_cast<const float4*>(W + (size_t)(k0 + kk) * BN + nq);
            Ws[kk][nq + 0] = v.x; Ws[kk][nq + 1] = v.y;
            Ws[kk][nq + 2] = v.z; Ws[kk][nq + 3] = v.w;
        }
        __syncthreads();

        #pragma unroll 8
        for (int k = 0; k < BKK; k++) {
            float a[4], b[6];
            #pragma unroll
            for (int r = 0; r < 4; r++) a[r] = Xs[k][ty * 4 + r];
            #pragma unroll
            for (int j = 0; j < 6; j++) b[j] = Ws[k][tx * 6 + j];
            #pragma unroll
            for (int r = 0; r < 4; r++)
                #pragma unroll
                for (int j = 0; j < 6; j++)
                    acc[r][j] += a[r] * b[j];
        }
        __syncthreads();
    }

    #pragma unroll
    for (int r = 0; r < 4; r++) {
        int row = row0 + ty * 4 + r;
        if (row < M) {
            #pragma unroll
            for (int j = 0; j < 6; j++) {
                int ncol = tx * 6 + j;
                float v = acc[r][j] + bias[ncol];
                if (do_relu) v = fmaxf(v, 0.f);
                C[(size_t)row * ldc + ncol] = v;
            }
        }
    }
}

// ---------------- launch ----------------
extern "C" void kernel_launch(void* const* d_in, const int* in_sizes, int n_in,
                              void* d_out, int out_size) {
    const float* x       = (const float*)d_in[0];
    const int*   ei      = (const int*)  d_in[1];
    const float* W_local = (const float*)d_in[2];
    const float* b_local = (const float*)d_in[3];
    const float* W_g1    = (const float*)d_in[4];
    const float* b_g1    = (const float*)d_in[5];
    const float* W_g2    = (const float*)d_in[6];
    const float* b_g2    = (const float*)d_in[7];
    const float* W_fuse  = (const float*)d_in[8];
    const float* b_fuse  = (const float*)d_in[9];
    float* out = (float*)d_out;

    int n = in_sizes[0] / FDIM; if (n > NMAX) n = NMAX;
    int e = in_sizes[1] / 2;    if (e > EMAX) e = EMAX;

    float *pA, *pG1, *pB, *pLG;
    cudaGetSymbolAddress((void**)&pA,  g_A);
    cudaGetSymbolAddress((void**)&pG1, g_G1);
    cudaGetSymbolAddress((void**)&pB,  g_B);
    cudaGetSymbolAddress((void**)&pLG, g_LG);

    const int tb = 256;
    k_zero <<<(n + tb - 1) / tb, tb>>>(n);
    k_count<<<(e + tb - 1) / tb, tb>>>(ei, e);
    k_dis  <<<(n + tb - 1) / tb, tb>>>(n);
    k_fill <<<(e + tb - 1) / tb, tb>>>(ei, e);

    int aggGrid  = (n + 7) / 8;
    int gemmGrid = (n + BM - 1) / BM;

    // A = P x
    k_agg<<<aggGrid, 256>>>(x, pA, n);
    // local = relu(A W_local + b)  -> LG[:, 0:96]
    k_gemm<<<gemmGrid, 256>>>(pA, FDIM, FDIM, W_local, b_local, pLG, 2 * FDIM, n, 1);
    // g1 = relu(A W_g1 + b)
    k_gemm<<<gemmGrid, 256>>>(pA, FDIM, FDIM, W_g1, b_g1, pG1, FDIM, n, 1);
    // B = P g1
    k_agg<<<aggGrid, 256>>>(pG1, pB, n);
    // g2 = relu(B W_g2 + b)  -> LG[:, 96:192]
    k_gemm<<<gemmGrid, 256>>>(pB, FDIM, FDIM, W_g2, b_g2, pLG + FDIM, 2 * FDIM, n, 1);
    // out = LG @ W_fuse + b_fuse
    k_gemm<<<gemmGrid, 256>>>(pLG, 2 * FDIM, 2 * FDIM, W_fuse, b_fuse, out, FDIM, n, 0);
}

// round 3
// speedup vs baseline: 1.1556x; 1.1556x over previous
#include <cuda_runtime.h>

#define NMAX 50000
#define EMAX 800000
#define FDIM 96
#define DEG_PAD 128

// ---------------- scratch (device globals: allocation-free) ----------------
__device__ int   g_deg[NMAX];
__device__ float g_dis[NMAX];
__device__ __align__(16) int   g_ell[(size_t)NMAX * DEG_PAD];
__device__ __align__(16) float g_A [(size_t)NMAX * FDIM];     // P x
__device__ __align__(16) float g_G1[(size_t)NMAX * FDIM];     // relu(A W_g1 + b)
__device__ __align__(16) float g_B [(size_t)NMAX * FDIM];     // P g1
__device__ __align__(16) float g_LG[(size_t)NMAX * 2 * FDIM]; // [local | g2]

// ---------------- packed f32x2 helpers (sm_100+) ----------------
__device__ __forceinline__ void ffma2(unsigned long long& d,
                                      unsigned long long a,
                                      unsigned long long b) {
    asm("fma.rn.f32x2 %0, %1, %2, %0;" : "+l"(d) : "l"(a), "l"(b));
}
__device__ __forceinline__ unsigned long long splat2(float x) {
    unsigned long long r;
    asm("mov.b64 %0, {%1, %1};" : "=l"(r) : "f"(x));
    return r;
}

// ---------------- degree / ELL build ----------------
__global__ void k_zero(int n) {
    int i = blockIdx.x * blockDim.x + threadIdx.x;
    if (i < n) g_deg[i] = 0;
}

// fill ELL; the atomic cursor doubles as the final degree count
__global__ void k_fill(const int* __restrict__ ei, int e_cnt) {
    int i = blockIdx.x * blockDim.x + threadIdx.x;
    int e0 = i * 2;
    if (e0 + 1 < e_cnt) {
        int2 s = *reinterpret_cast<const int2*>(ei + e0);
        int2 d = *reinterpret_cast<const int2*>(ei + e_cnt + e0);
        int p0 = atomicAdd(&g_deg[d.x], 1);
        if (p0 < DEG_PAD) g_ell[(size_t)d.x * DEG_PAD + p0] = s.x;
        int p1 = atomicAdd(&g_deg[d.y], 1);
        if (p1 < DEG_PAD) g_ell[(size_t)d.y * DEG_PAD + p1] = s.y;
    } else if (e0 < e_cnt) {
        int s = ei[e0], d = ei[e_cnt + e0];
        int p = atomicAdd(&g_deg[d], 1);
        if (p < DEG_PAD) g_ell[(size_t)d * DEG_PAD + p] = s;
    }
}

__global__ void k_dis(int n) {
    int i = blockIdx.x * blockDim.x + threadIdx.x;
    if (i < n) g_dis[i] = rsqrtf((float)(g_deg[i] + 1));  // +1 self-loop
}

// ---------------- aggregation: out[i] = dis[i]*( sum_e dis[src] h[src] + dis[i] h[i] )
__global__ void __launch_bounds__(256) k_agg(const float* __restrict__ h,
                                             float* __restrict__ out, int n) {
    int warp = blockIdx.x * 8 + (threadIdx.x >> 5);
    int lane = threadIdx.x & 31;
    if (warp >= n) return;

    int cnt = g_deg[warp];
    cnt = cnt < DEG_PAD ? cnt : DEG_PAD;
    float di = g_dis[warp];
    const int* row = g_ell + (size_t)warp * DEG_PAD;

    const float* hs = h + (size_t)warp * FDIM;   // self loop (norm = dis^2)
    float a0 = di * hs[lane];
    float a1 = di * hs[lane + 32];
    float a2 = di * hs[lane + 64];

    for (int base = 0; base < cnt; base += 32) {
        int take = cnt - base; if (take > 32) take = 32;
        int s = 0; float w = 0.f;
        if (lane < take) { s = row[base + lane]; w = g_dis[s]; }
        #pragma unroll 8
        for (int j = 0; j < take; j++) {
            int   ss = __shfl_sync(0xffffffffu, s, j);
            float ww = __shfl_sync(0xffffffffu, w, j);
            const float* hp = h + (size_t)ss * FDIM;
            a0 += ww * hp[lane];
            a1 += ww * hp[lane + 32];
            a2 += ww * hp[lane + 64];
        }
    }
    float* op = out + (size_t)warp * FDIM;
    op[lane]      = di * a0;
    op[lane + 32] = di * a1;
    op[lane + 64] = di * a2;
}

// ---------------- GEMM: C[M x 96] = act( X[M x K] @ W[K x 96] + b )
// BM=128, BN=96, BK=32; 256 threads; per-thread 8 rows x 6 cols, accumulated
// as 8x3 packed f32x2 (pairs along columns -> b pairs load directly via LDS.64)
#define BM 128
#define BKK 32
#define BN 96
#define XS_STRIDE 132   // BM+4: 16B-aligned rows, conflict-reduced

__global__ void __launch_bounds__(256, 2)
k_gemm(const float* __restrict__ X, int ldx, int K,
       const float* __restrict__ W,
       const float* __restrict__ bias,
       float* __restrict__ C, int ldc,
       int M, int do_relu) {
    __shared__ float Xs[BKK * XS_STRIDE];   // transposed X tile: Xs[k][m]
    __shared__ float Ws[BKK * BN];          // Ws[k][n]

    int t  = threadIdx.x;
    int tx = t & 15;        // col group: cols tx*6 .. tx*6+5
    int ty = t >> 4;        // row group: rows ty*8 .. ty*8+7
    int row0 = blockIdx.x * BM;

    unsigned long long acc[8][3];
    #pragma unroll
    for (int r = 0; r < 8; r++)
        #pragma unroll
        for (int j = 0; j < 3; j++) acc[r][j] = 0ull;

    for (int k0 = 0; k0 < K; k0 += BKK) {
        // load X tile (128 x 32) as float4, store transposed
        #pragma unroll
        for (int i = 0; i < 4; i++) {
            int idx = t + i * 256;          // 0..1023
            int m   = idx >> 3;             // 8 float4 per row
            int kq  = (idx & 7) << 2;
            float4 v = make_float4(0.f, 0.f, 0.f, 0.f);
            int row = row0 + m;
            if (row < M)
                v = *reinterpret_cast<const float4*>(X + (size_t)row * ldx + k0 + kq);
            Xs[(kq + 0) * XS_STRIDE + m] = v.x;
            Xs[(kq + 1) * XS_STRIDE + m] = v.y;
            Xs[(kq + 2) * XS_STRIDE + m] = v.z;
            Xs[(kq + 3) * XS_STRIDE + m] = v.w;
        }
        // load W tile (32 x 96) as float4
        #pragma unroll
        for (int i = 0; i < 3; i++) {
            int idx = t + i * 256;          // 0..767
            int kk  = idx / 24;
            int nq  = (idx % 24) << 2;
            *reinterpret_cast<float4*>(&Ws[kk * BN + nq]) =
                *reinterpret_cast<const float4*>(W + (size_t)(k0 + kk) * BN + nq);
        }
        __syncthreads();

        #pragma unroll 16
        for (int k = 0; k < BKK; k++) {
            // a: 8 rows via two LDS.128 (broadcast within warp)
            float4 a0 = *reinterpret_cast<const float4*>(&Xs[k * XS_STRIDE + ty * 8]);
            float4 a1 = *reinterpret_cast<const float4*>(&Xs[k * XS_STRIDE + ty * 8 + 4]);
            // b: 3 packed col-pairs via LDS.64
            unsigned long long b0 = *reinterpret_cast<const unsigned long long*>(&Ws[k * BN + tx * 6]);
            unsigned long long b1 = *reinterpret_cast<const unsigned long long*>(&Ws[k * BN + tx * 6 + 2]);
            unsigned long long b2 = *reinterpret_cast<const unsigned long long*>(&Ws[k * BN + tx * 6 + 4]);

            float ar[8] = {a0.x, a0.y, a0.z, a0.w, a1.x, a1.y, a1.z, a1.w};
            #pragma unroll
            for (int r = 0; r < 8; r++) {
                unsigned long long as = splat2(ar[r]);
                ffma2(acc[r][0], as, b0);
                ffma2(acc[r][1], as, b1);
                ffma2(acc[r][2], as, b2);
            }
        }
        __syncthreads();
    }

    // epilogue: unpack pairs, add bias, relu, float2 stores
    float2 bb[3];
    #pragma unroll
    for (int j = 0; j < 3; j++)
        bb[j] = *reinterpret_cast<const float2*>(bias + tx * 6 + j * 2);

    #pragma unroll
    for (int r = 0; r < 8; r++) {
        int row = row0 + ty * 8 + r;
        if (row < M) {
            float* cp = C + (size_t)row * ldc + tx * 6;
            #pragma unroll
            for (int j = 0; j < 3; j++) {
                float2 v = *reinterpret_cast<float2*>(&acc[r][j]);
                v.x += bb[j].x; v.y += bb[j].y;
                if (do_relu) { v.x = fmaxf(v.x, 0.f); v.y = fmaxf(v.y, 0.f); }
                *reinterpret_cast<float2*>(cp + j * 2) = v;
            }
        }
    }
}

// ---------------- launch ----------------
extern "C" void kernel_launch(void* const* d_in, const int* in_sizes, int n_in,
                              void* d_out, int out_size) {
    const float* x       = (const float*)d_in[0];
    const int*   ei      = (const int*)  d_in[1];
    const float* W_local = (const float*)d_in[2];
    const float* b_local = (const float*)d_in[3];
    const float* W_g1    = (const float*)d_in[4];
    const float* b_g1    = (const float*)d_in[5];
    const float* W_g2    = (const float*)d_in[6];
    const float* b_g2    = (const float*)d_in[7];
    const float* W_fuse  = (const float*)d_in[8];
    const float* b_fuse  = (const float*)d_in[9];
    float* out = (float*)d_out;

    int n = in_sizes[0] / FDIM; if (n > NMAX) n = NMAX;
    int e = in_sizes[1] / 2;    if (e > EMAX) e = EMAX;

    float *pA, *pG1, *pB, *pLG;
    cudaGetSymbolAddress((void**)&pA,  g_A);
    cudaGetSymbolAddress((void**)&pG1, g_G1);
    cudaGetSymbolAddress((void**)&pB,  g_B);
    cudaGetSymbolAddress((void**)&pLG, g_LG);

    const int tb = 256;
    int ePairs = (e + 1) / 2;
    k_zero<<<(n + tb - 1) / tb, tb>>>(n);
    k_fill<<<(ePairs + tb - 1) / tb, tb>>>(ei, e);
    k_dis <<<(n + tb - 1) / tb, tb>>>(n);

    int aggGrid  = (n + 7) / 8;
    int gemmGrid = (n + BM - 1) / BM;

    // A = P x
    k_agg<<<aggGrid, 256>>>(x, pA, n);
    // local = relu(A W_local + b)  -> LG[:, 0:96]
    k_gemm<<<gemmGrid, 256>>>(pA, FDIM, FDIM, W_local, b_local, pLG, 2 * FDIM, n, 1);
    // g1 = relu(A W_g1 + b)
    k_gemm<<<gemmGrid, 256>>>(pA, FDIM, FDIM, W_g1, b_g1, pG1, FDIM, n, 1);
    // B = P g1
    k_agg<<<aggGrid, 256>>>(pG1, pB, n);
    // g2 = relu(B W_g2 + b)  -> LG[:, 96:192]
    k_gemm<<<gemmGrid, 256>>>(pB, FDIM, FDIM, W_g2, b_g2, pLG + FDIM, 2 * FDIM, n, 1);
    // out = LG @ W_fuse + b_fuse
    k_gemm<<<gemmGrid, 256>>>(pLG, 2 * FDIM, 2 * FDIM, W_fuse, b_fuse, out, FDIM, n, 0);
}

// round 6
// speedup vs baseline: 1.2683x; 1.0975x over previous
#include <cuda_runtime.h>
#include <cuda_bf16.h>
#include <cstdint>

#define NMAX 50000
#define EMAX 800000
#define FDIM 96
#define DEG_PAD 128

// ---------------- scratch (device globals: allocation-free) ----------------
__device__ int   g_deg[NMAX];
__device__ float g_dis[NMAX];
__device__ __align__(16) int   g_ell[(size_t)NMAX * DEG_PAD];
__device__ __align__(16) float g_A [(size_t)NMAX * FDIM];   // P x
__device__ __align__(16) float g_G1[(size_t)NMAX * FDIM];   // relu(A W_g1 + b)
__device__ __align__(16) float g_Bv[(size_t)NMAX * FDIM];   // P g1
__device__ __align__(16) float g_L [(size_t)NMAX * FDIM];   // local
__device__ __align__(16) float g_G2[(size_t)NMAX * FDIM];   // g2
// precomputed B fragments in mma-lane layout: [img][kt<6][nt<12][lane<32]
// uint4 = {b_hi reg0, b_hi reg1, b_lo reg0, b_lo reg1}
// img 0=W_local 1=W_g1 2=W_g2 3=W_fuse[0:96,:] 4=W_fuse[96:192,:]
#define FRAG_PER_IMG (6 * 12 * 32)
__device__ __align__(16) uint4 g_frag[5 * FRAG_PER_IMG];

// ---------------- degree / ELL build ----------------
__global__ void k_zero(int n) {
    int i = blockIdx.x * blockDim.x + threadIdx.x;
    if (i < n) g_deg[i] = 0;
}
__global__ void k_fill(const int* __restrict__ ei, int e_cnt) {
    int i = blockIdx.x * blockDim.x + threadIdx.x;
    int e0 = i * 4;
    if (e0 + 3 < e_cnt) {
        int4 s = *reinterpret_cast<const int4*>(ei + e0);
        int4 d = *reinterpret_cast<const int4*>(ei + e_cnt + e0);
        int p;
        p = atomicAdd(&g_deg[d.x], 1); if (p < DEG_PAD) g_ell[(size_t)d.x * DEG_PAD + p] = s.x;
        p = atomicAdd(&g_deg[d.y], 1); if (p < DEG_PAD) g_ell[(size_t)d.y * DEG_PAD + p] = s.y;
        p = atomicAdd(&g_deg[d.z], 1); if (p < DEG_PAD) g_ell[(size_t)d.z * DEG_PAD + p] = s.z;
        p = atomicAdd(&g_deg[d.w], 1); if (p < DEG_PAD) g_ell[(size_t)d.w * DEG_PAD + p] = s.w;
    } else {
        for (int e = e0; e < e_cnt && e < e0 + 4; e++) {
            int s = ei[e], d = ei[e_cnt + e];
            int p = atomicAdd(&g_deg[d], 1);
            if (p < DEG_PAD) g_ell[(size_t)d * DEG_PAD + p] = s;
        }
    }
}
__global__ void k_dis(int n) {
    int i = blockIdx.x * blockDim.x + threadIdx.x;
    if (i < n) g_dis[i] = rsqrtf((float)(g_deg[i] + 1));
}

// ---------------- bf16 hi/lo packing helpers ----------------
__device__ __forceinline__ uint32_t pack_hi2(float a, float b) {
    __nv_bfloat162 h = __floats2bfloat162_rn(a, b);
    return *reinterpret_cast<uint32_t*>(&h);
}
__device__ __forceinline__ uint32_t pack_lo2(float a, float b) {
    __nv_bfloat162 h = __floats2bfloat162_rn(a, b);
    float2 f = __bfloat1622float2(h);
    __nv_bfloat162 l = __floats2bfloat162_rn(a - f.x, b - f.y);
    return *reinterpret_cast<uint32_t*>(&l);
}

// ---------------- weight prep: B fragments (mma m16n8k16 col-major B layout) ----------------
__global__ void k_prepB(const float* __restrict__ Wl, const float* __restrict__ Wg1,
                        const float* __restrict__ Wg2, const float* __restrict__ Wf) {
    int i = blockIdx.x * blockDim.x + threadIdx.x;
    if (i >= 5 * FRAG_PER_IMG) return;
    int lane = i & 31;
    int nt   = (i >> 5) % 12;
    int kt   = ((i >> 5) / 12) % 6;
    int img  = i / FRAG_PER_IMG;

    int n  = nt * 8 + (lane >> 2);
    int k0 = kt * 16 + (lane & 3) * 2;

    const float* W;
    int koff = 0;
    if      (img == 0) W = Wl;
    else if (img == 1) W = Wg1;
    else if (img == 2) W = Wg2;
    else if (img == 3) W = Wf;
    else               { W = Wf; koff = 96; }

    float w0 = W[(size_t)(koff + k0)     * 96 + n];
    float w1 = W[(size_t)(koff + k0 + 1) * 96 + n];
    float w8 = W[(size_t)(koff + k0 + 8) * 96 + n];
    float w9 = W[(size_t)(koff + k0 + 9) * 96 + n];

    uint4 o;
    o.x = pack_hi2(w0, w1);
    o.y = pack_hi2(w8, w9);
    o.z = pack_lo2(w0, w1);
    o.w = pack_lo2(w8, w9);
    g_frag[i] = o;
}

// ---------------- aggregation ----------------
__global__ void __launch_bounds__(256) k_agg(const float* __restrict__ h,
                                             float* __restrict__ out, int n) {
    int warp = blockIdx.x * 8 + (threadIdx.x >> 5);
    int lane = threadIdx.x & 31;
    if (warp >= n) return;

    int cnt = g_deg[warp];
    cnt = cnt < DEG_PAD ? cnt : DEG_PAD;
    float di = g_dis[warp];
    const int* row = g_ell + (size_t)warp * DEG_PAD;

    const float* hs = h + (size_t)warp * FDIM;
    float a0 = di * hs[lane];
    float a1 = di * hs[lane + 32];
    float a2 = di * hs[lane + 64];

    for (int base = 0; base < cnt; base += 32) {
        int take = cnt - base; if (take > 32) take = 32;
        int s = 0; float w = 0.f;
        if (lane < take) { s = row[base + lane]; w = g_dis[s]; }
        #pragma unroll 8
        for (int j = 0; j < take; j++) {
            int   ss = __shfl_sync(0xffffffffu, s, j);
            float ww = __shfl_sync(0xffffffffu, w, j);
            const float* hp = h + (size_t)ss * FDIM;
            a0 += ww * hp[lane];
            a1 += ww * hp[lane + 32];
            a2 += ww * hp[lane + 64];
        }
    }
    float* op = out + (size_t)warp * FDIM;
    op[lane]      = di * a0;
    op[lane + 32] = di * a1;
    op[lane + 64] = di * a2;
}

// ---------------- mma.sync bf16 GEMM (HMMA path, portable PTX) ----------------
__device__ __forceinline__ void mma16816(float acc[4], const uint32_t a[4],
                                         uint32_t b0, uint32_t b1) {
    asm volatile(
        "mma.sync.aligned.m16n8k16.row.col.f32.bf16.bf16.f32 "
        "{%0,%1,%2,%3}, {%4,%5,%6,%7}, {%8,%9}, {%0,%1,%2,%3};"
        : "+f"(acc[0]), "+f"(acc[1]), "+f"(acc[2]), "+f"(acc[3])
        : "r"(a[0]), "r"(a[1]), "r"(a[2]), "r"(a[3]), "r"(b0), "r"(b1));
}

// one K=96 chunk: acc[nt] += X[rows, 0:96] @ W_chunk
__device__ __forceinline__ void gemm_chunk(const float* __restrict__ X,
                                           const uint4* __restrict__ F,
                                           int row0, int lane, int M,
                                           float acc[12][4]) {
    int r  = lane >> 2;
    int cq = (lane & 3) * 2;
    int ra = row0 + r, rb = row0 + r + 8;
    const float2 z = make_float2(0.f, 0.f);

    #pragma unroll
    for (int kt = 0; kt < 6; kt++) {
        int kb = kt * 16 + cq;
        float2 v00 = (ra < M) ? *reinterpret_cast<const float2*>(X + (size_t)ra * FDIM + kb)     : z;
        float2 v01 = (ra < M) ? *reinterpret_cast<const float2*>(X + (size_t)ra * FDIM + kb + 8) : z;
        float2 v10 = (rb < M) ? *reinterpret_cast<const float2*>(X + (size_t)rb * FDIM + kb)     : z;
        float2 v11 = (rb < M) ? *reinterpret_cast<const float2*>(X + (size_t)rb * FDIM + kb + 8) : z;

        uint32_t ah[4] = { pack_hi2(v00.x, v00.y), pack_hi2(v10.x, v10.y),
                           pack_hi2(v01.x, v01.y), pack_hi2(v11.x, v11.y) };
        uint32_t al[4] = { pack_lo2(v00.x, v00.y), pack_lo2(v10.x, v10.y),
                           pack_lo2(v01.x, v01.y), pack_lo2(v11.x, v11.y) };

        const uint4* fp = F + (size_t)kt * 12 * 32 + lane;
        #pragma unroll
        for (int nt = 0; nt < 12; nt++) {
            uint4 b = fp[nt * 32];
            mma16816(acc[nt], ah, b.x, b.y);   // hi*hi
            mma16816(acc[nt], ah, b.z, b.w);   // hi*lo
            mma16816(acc[nt], al, b.x, b.y);   // lo*hi
        }
    }
}

// C[M x 96] = act( X1 @ W1 (+ X2 @ W2) + bias );  BM=128, 8 warps x 16 rows
__global__ void __launch_bounds__(256)
k_mgemm(const float* __restrict__ X1, const float* __restrict__ X2,
        const uint4* __restrict__ F1, const uint4* __restrict__ F2,
        const float* __restrict__ bias, float* __restrict__ C,
        int M, int relu) {
    int lane = threadIdx.x & 31, warp = threadIdx.x >> 5;
    int row0 = blockIdx.x * 128 + warp * 16;

    float acc[12][4];
    #pragma unroll
    for (int nt = 0; nt < 12; nt++)
        #pragma unroll
        for (int j = 0; j < 4; j++) acc[nt][j] = 0.f;

    gemm_chunk(X1, F1, row0, lane, M, acc);
    if (X2 != nullptr) gemm_chunk(X2, F2, row0, lane, M, acc);

    int r  = lane >> 2;
    int cq = (lane & 3) * 2;
    int ra = row0 + r, rb = row0 + r + 8;
    #pragma unroll
    for (int nt = 0; nt < 12; nt++) {
        int col = nt * 8 + cq;
        float2 bb = *reinterpret_cast<const float2*>(bias + col);
        float2 va = make_float2(acc[nt][0] + bb.x, acc[nt][1] + bb.y);
        float2 vb = make_float2(acc[nt][2] + bb.x, acc[nt][3] + bb.y);
        if (relu) {
            va.x = fmaxf(va.x, 0.f); va.y = fmaxf(va.y, 0.f);
            vb.x = fmaxf(vb.x, 0.f); vb.y = fmaxf(vb.y, 0.f);
        }
        if (ra < M) *reinterpret_cast<float2*>(C + (size_t)ra * FDIM + col) = va;
        if (rb < M) *reinterpret_cast<float2*>(C + (size_t)rb * FDIM + col) = vb;
    }
}

// ---------------- launch ----------------
extern "C" void kernel_launch(void* const* d_in, const int* in_sizes, int n_in,
                              void* d_out, int out_size) {
    const float* x       = (const float*)d_in[0];
    const int*   ei      = (const int*)  d_in[1];
    const float* W_local = (const float*)d_in[2];
    const float* b_local = (const float*)d_in[3];
    const float* W_g1    = (const float*)d_in[4];
    const float* b_g1    = (const float*)d_in[5];
    const float* W_g2    = (const float*)d_in[6];
    const float* b_g2    = (const float*)d_in[7];
    const float* W_fuse  = (const float*)d_in[8];
    const float* b_fuse  = (const float*)d_in[9];
    float* out = (float*)d_out;

    int n = in_sizes[0] / FDIM; if (n > NMAX) n = NMAX;
    int e = in_sizes[1] / 2;    if (e > EMAX) e = EMAX;

    float *pA, *pG1, *pBv, *pL, *pG2;
    uint4* pF;
    cudaGetSymbolAddress((void**)&pA,  g_A);
    cudaGetSymbolAddress((void**)&pG1, g_G1);
    cudaGetSymbolAddress((void**)&pBv, g_Bv);
    cudaGetSymbolAddress((void**)&pL,  g_L);
    cudaGetSymbolAddress((void**)&pG2, g_G2);
    cudaGetSymbolAddress((void**)&pF,  g_frag);

    const int tb = 256;
    int eq = (e + 3) / 4;
    k_zero <<<(n + tb - 1) / tb, tb>>>(n);
    k_fill <<<(eq + tb - 1) / tb, tb>>>(ei, e);
    k_dis  <<<(n + tb - 1) / tb, tb>>>(n);
    k_prepB<<<(5 * FRAG_PER_IMG + tb - 1) / tb, tb>>>(W_local, W_g1, W_g2, W_fuse);

    int aggGrid = (n + 7) / 8;
    int gGrid   = (n + 127) / 128;

    // A = P x
    k_agg<<<aggGrid, 256>>>(x, pA, n);
    // local = relu(A W_local + b)
    k_mgemm<<<gGrid, 256>>>(pA, nullptr, pF + 0 * FRAG_PER_IMG, nullptr,
                            b_local, pL, n, 1);
    // g1 = relu(A W_g1 + b)
    k_mgemm<<<gGrid, 256>>>(pA, nullptr, pF + 1 * FRAG_PER_IMG, nullptr,
                            b_g1, pG1, n, 1);
    // B = P g1
    k_agg<<<aggGrid, 256>>>(pG1, pBv, n);
    // g2 = relu(B W_g2 + b)
    k_mgemm<<<gGrid, 256>>>(pBv, nullptr, pF + 2 * FRAG_PER_IMG, nullptr,
                            b_g2, pG2, n, 1);
    // out = local @ Wf_top + g2 @ Wf_bot + b_fuse
    k_mgemm<<<gGrid, 256>>>(pL, pG2, pF + 3 * FRAG_PER_IMG, pF + 4 * FRAG_PER_IMG,
                            b_fuse, out, n, 0);
}

// round 7
// speedup vs baseline: 1.3277x; 1.0468x over previous
#include <cuda_runtime.h>
#include <cuda_bf16.h>
#include <cstdint>

#define NMAX 50000
#define EMAX 800000
#define FDIM 96
#define DEG_PAD 128

// ---------------- scratch (device globals: allocation-free) ----------------
__device__ int   g_deg[NMAX];
__device__ float g_dis[NMAX];
__device__ __align__(16) int   g_ell[(size_t)NMAX * DEG_PAD];
__device__ __align__(16) float g_Xs[(size_t)NMAX * FDIM];   // dis * x
__device__ __align__(16) float g_A [(size_t)NMAX * FDIM];   // P x
__device__ __align__(16) float g_G1[(size_t)NMAX * FDIM];   // dis * relu(A W_g1 + b)
__device__ __align__(16) float g_Bv[(size_t)NMAX * FDIM];   // P g1
__device__ __align__(16) float g_L [(size_t)NMAX * FDIM];   // local
// precomputed B fragments in mma-lane layout: [img][kt<6][nt<12][lane<32]
// uint4 = {b_hi reg0, b_hi reg1, b_lo reg0, b_lo reg1}
// img 0=W_local 1=W_g1 2=W_g2 3=W_fuse[0:96,:] 4=W_fuse[96:192,:]
#define FRAG_PER_IMG (6 * 12 * 32)
__device__ __align__(16) uint4 g_frag[5 * FRAG_PER_IMG];

// ---------------- degree / ELL build ----------------
__global__ void k_zero(int n) {
    int i = blockIdx.x * blockDim.x + threadIdx.x;
    if (i < n) g_deg[i] = 0;
}
__global__ void k_fill(const int* __restrict__ ei, int e_cnt) {
    int i = blockIdx.x * blockDim.x + threadIdx.x;
    int e0 = i * 4;
    if (e0 + 3 < e_cnt) {
        int4 s = *reinterpret_cast<const int4*>(ei + e0);
        int4 d = *reinterpret_cast<const int4*>(ei + e_cnt + e0);
        int p;
        p = atomicAdd(&g_deg[d.x], 1); if (p < DEG_PAD) g_ell[(size_t)d.x * DEG_PAD + p] = s.x;
        p = atomicAdd(&g_deg[d.y], 1); if (p < DEG_PAD) g_ell[(size_t)d.y * DEG_PAD + p] = s.y;
        p = atomicAdd(&g_deg[d.z], 1); if (p < DEG_PAD) g_ell[(size_t)d.z * DEG_PAD + p] = s.z;
        p = atomicAdd(&g_deg[d.w], 1); if (p < DEG_PAD) g_ell[(size_t)d.w * DEG_PAD + p] = s.w;
    } else {
        for (int e = e0; e < e_cnt && e < e0 + 4; e++) {
            int s = ei[e], d = ei[e_cnt + e];
            int p = atomicAdd(&g_deg[d], 1);
            if (p < DEG_PAD) g_ell[(size_t)d * DEG_PAD + p] = s;
        }
    }
}
__global__ void k_dis(int n) {
    int i = blockIdx.x * blockDim.x + threadIdx.x;
    if (i < n) g_dis[i] = rsqrtf((float)(g_deg[i] + 1));
}
// x' = dis * x  (float4 per thread)
__global__ void k_scale(const float* __restrict__ x, int n) {
    int i = blockIdx.x * blockDim.x + threadIdx.x;
    if (i >= n * 24) return;
    int row = i / 24, c4 = (i % 24) * 4;
    float d = g_dis[row];
    float4 v = *reinterpret_cast<const float4*>(x + (size_t)row * FDIM + c4);
    v.x *= d; v.y *= d; v.z *= d; v.w *= d;
    *reinterpret_cast<float4*>(g_Xs + (size_t)row * FDIM + c4) = v;
}

// ---------------- bf16 hi/lo packing helpers ----------------
__device__ __forceinline__ uint32_t pack_hi2(float a, float b) {
    __nv_bfloat162 h = __floats2bfloat162_rn(a, b);
    return *reinterpret_cast<uint32_t*>(&h);
}
__device__ __forceinline__ uint32_t pack_lo2(float a, float b) {
    __nv_bfloat162 h = __floats2bfloat162_rn(a, b);
    float2 f = __bfloat1622float2(h);
    __nv_bfloat162 l = __floats2bfloat162_rn(a - f.x, b - f.y);
    return *reinterpret_cast<uint32_t*>(&l);
}

// ---------------- weight prep: B fragments (mma m16n8k16 col-major B layout) ----------------
__global__ void k_prepB(const float* __restrict__ Wl, const float* __restrict__ Wg1,
                        const float* __restrict__ Wg2, const float* __restrict__ Wf) {
    int i = blockIdx.x * blockDim.x + threadIdx.x;
    if (i >= 5 * FRAG_PER_IMG) return;
    int lane = i & 31;
    int nt   = (i >> 5) % 12;
    int kt   = ((i >> 5) / 12) % 6;
    int img  = i / FRAG_PER_IMG;

    int n  = nt * 8 + (lane >> 2);
    int k0 = kt * 16 + (lane & 3) * 2;

    const float* W;
    int koff = 0;
    if      (img == 0) W = Wl;
    else if (img == 1) W = Wg1;
    else if (img == 2) W = Wg2;
    else if (img == 3) W = Wf;
    else               { W = Wf; koff = 96; }

    float w0 = W[(size_t)(koff + k0)     * 96 + n];
    float w1 = W[(size_t)(koff + k0 + 1) * 96 + n];
    float w8 = W[(size_t)(koff + k0 + 8) * 96 + n];
    float w9 = W[(size_t)(koff + k0 + 9) * 96 + n];

    uint4 o;
    o.x = pack_hi2(w0, w1);
    o.y = pack_hi2(w8, w9);
    o.z = pack_lo2(w0, w1);
    o.w = pack_lo2(w8, w9);
    g_frag[i] = o;
}

// ---------------- aggregation: out[i] = dis[i]*( sum_src h'[src] + h'[i] ), h' prescaled
__global__ void __launch_bounds__(256) k_agg(const float* __restrict__ h,
                                             float* __restrict__ out, int n) {
    int warp = blockIdx.x * 8 + (threadIdx.x >> 5);
    int lane = threadIdx.x & 31;
    if (warp >= n) return;

    int cnt = g_deg[warp];
    cnt = cnt < DEG_PAD ? cnt : DEG_PAD;
    float di = g_dis[warp];
    const int* row = g_ell + (size_t)warp * DEG_PAD;

    const float* hs = h + (size_t)warp * FDIM;   // self term (already scaled)
    float a0 = hs[lane];
    float a1 = hs[lane + 32];
    float a2 = hs[lane + 64];

    for (int base = 0; base < cnt; base += 32) {
        int take = cnt - base; if (take > 32) take = 32;
        int s = 0;
        if (lane < take) s = row[base + lane];
        #pragma unroll 8
        for (int j = 0; j < take; j++) {
            int ss = __shfl_sync(0xffffffffu, s, j);
            const float* hp = h + (size_t)ss * FDIM;
            a0 += hp[lane];
            a1 += hp[lane + 32];
            a2 += hp[lane + 64];
        }
    }
    float* op = out + (size_t)warp * FDIM;
    op[lane]      = di * a0;
    op[lane + 32] = di * a1;
    op[lane + 64] = di * a2;
}

// ---------------- mma.sync bf16 GEMM (HMMA path, portable PTX) ----------------
__device__ __forceinline__ void mma16816(float acc[4], const uint32_t a[4],
                                         uint32_t b0, uint32_t b1) {
    asm volatile(
        "mma.sync.aligned.m16n8k16.row.col.f32.bf16.bf16.f32 "
        "{%0,%1,%2,%3}, {%4,%5,%6,%7}, {%8,%9}, {%0,%1,%2,%3};"
        : "+f"(acc[0]), "+f"(acc[1]), "+f"(acc[2]), "+f"(acc[3])
        : "r"(a[0]), "r"(a[1]), "r"(a[2]), "r"(a[3]), "r"(b0), "r"(b1));
}

// one K=96 chunk into acc
__device__ __forceinline__ void gemm_chunk(const float* __restrict__ X,
                                           const uint4* __restrict__ F,
                                           int row0, int lane, int M,
                                           float acc[12][4]) {
    int r  = lane >> 2;
    int cq = (lane & 3) * 2;
    int ra = row0 + r, rb = row0 + r + 8;
    const float2 z = make_float2(0.f, 0.f);

    #pragma unroll
    for (int kt = 0; kt < 6; kt++) {
        int kb = kt * 16 + cq;
        float2 v00 = (ra < M) ? *reinterpret_cast<const float2*>(X + (size_t)ra * FDIM + kb)     : z;
        float2 v01 = (ra < M) ? *reinterpret_cast<const float2*>(X + (size_t)ra * FDIM + kb + 8) : z;
        float2 v10 = (rb < M) ? *reinterpret_cast<const float2*>(X + (size_t)rb * FDIM + kb)     : z;
        float2 v11 = (rb < M) ? *reinterpret_cast<const float2*>(X + (size_t)rb * FDIM + kb + 8) : z;

        uint32_t ah[4] = { pack_hi2(v00.x, v00.y), pack_hi2(v10.x, v10.y),
                           pack_hi2(v01.x, v01.y), pack_hi2(v11.x, v11.y) };
        uint32_t al[4] = { pack_lo2(v00.x, v00.y), pack_lo2(v10.x, v10.y),
                           pack_lo2(v01.x, v01.y), pack_lo2(v11.x, v11.y) };

        const uint4* fp = F + (size_t)kt * 12 * 32 + lane;
        #pragma unroll
        for (int nt = 0; nt < 12; nt++) {
            uint4 b = fp[nt * 32];
            mma16816(acc[nt], ah, b.x, b.y);   // hi*hi
            mma16816(acc[nt], ah, b.z, b.w);   // hi*lo
            mma16816(acc[nt], al, b.x, b.y);   // lo*hi
        }
    }
}

// dual-output GEMM sharing input A: C1 = relu(A W1 + b1); C2 = dis * relu(A W2 + b2)
__global__ void __launch_bounds__(256)
k_dualgemm(const float* __restrict__ X,
           const uint4* __restrict__ F1, const uint4* __restrict__ F2,
           const float* __restrict__ bias1, const float* __restrict__ bias2,
           float* __restrict__ C1, float* __restrict__ C2, int M) {
    int lane = threadIdx.x & 31, warp = threadIdx.x >> 5;
    int row0 = blockIdx.x * 128 + warp * 16;

    int r  = lane >> 2;
    int cq = (lane & 3) * 2;
    int ra = row0 + r, rb = row0 + r + 8;
    const float2 z = make_float2(0.f, 0.f);

    float acc1[12][4], acc2[12][4];
    #pragma unroll
    for (int nt = 0; nt < 12; nt++)
        #pragma unroll
        for (int j = 0; j < 4; j++) { acc1[nt][j] = 0.f; acc2[nt][j] = 0.f; }

    #pragma unroll
    for (int kt = 0; kt < 6; kt++) {
        int kb = kt * 16 + cq;
        float2 v00 = (ra < M) ? *reinterpret_cast<const float2*>(X + (size_t)ra * FDIM + kb)     : z;
        float2 v01 = (ra < M) ? *reinterpret_cast<const float2*>(X + (size_t)ra * FDIM + kb + 8) : z;
        float2 v10 = (rb < M) ? *reinterpret_cast<const float2*>(X + (size_t)rb * FDIM + kb)     : z;
        float2 v11 = (rb < M) ? *reinterpret_cast<const float2*>(X + (size_t)rb * FDIM + kb + 8) : z;

        uint32_t ah[4] = { pack_hi2(v00.x, v00.y), pack_hi2(v10.x, v10.y),
                           pack_hi2(v01.x, v01.y), pack_hi2(v11.x, v11.y) };
        uint32_t al[4] = { pack_lo2(v00.x, v00.y), pack_lo2(v10.x, v10.y),
                           pack_lo2(v01.x, v01.y), pack_lo2(v11.x, v11.y) };

        const uint4* fp1 = F1 + (size_t)kt * 12 * 32 + lane;
        const uint4* fp2 = F2 + (size_t)kt * 12 * 32 + lane;
        #pragma unroll
        for (int nt = 0; nt < 12; nt++) {
            uint4 b1 = fp1[nt * 32];
            mma16816(acc1[nt], ah, b1.x, b1.y);
            mma16816(acc1[nt], ah, b1.z, b1.w);
            mma16816(acc1[nt], al, b1.x, b1.y);
            uint4 b2 = fp2[nt * 32];
            mma16816(acc2[nt], ah, b2.x, b2.y);
            mma16816(acc2[nt], ah, b2.z, b2.w);
            mma16816(acc2[nt], al, b2.x, b2.y);
        }
    }

    float da = (ra < M) ? g_dis[ra] : 0.f;
    float db = (rb < M) ? g_dis[rb] : 0.f;
    #pragma unroll
    for (int nt = 0; nt < 12; nt++) {
        int col = nt * 8 + cq;
        float2 bb1 = *reinterpret_cast<const float2*>(bias1 + col);
        float2 bb2 = *reinterpret_cast<const float2*>(bias2 + col);
        float2 va, vb;
        va.x = fmaxf(acc1[nt][0] + bb1.x, 0.f); va.y = fmaxf(acc1[nt][1] + bb1.y, 0.f);
        vb.x = fmaxf(acc1[nt][2] + bb1.x, 0.f); vb.y = fmaxf(acc1[nt][3] + bb1.y, 0.f);
        if (ra < M) *reinterpret_cast<float2*>(C1 + (size_t)ra * FDIM + col) = va;
        if (rb < M) *reinterpret_cast<float2*>(C1 + (size_t)rb * FDIM + col) = vb;
        va.x = da * fmaxf(acc2[nt][0] + bb2.x, 0.f); va.y = da * fmaxf(acc2[nt][1] + bb2.y, 0.f);
        vb.x = db * fmaxf(acc2[nt][2] + bb2.x, 0.f); vb.y = db * fmaxf(acc2[nt][3] + bb2.y, 0.f);
        if (ra < M) *reinterpret_cast<float2*>(C2 + (size_t)ra * FDIM + col) = va;
        if (rb < M) *reinterpret_cast<float2*>(C2 + (size_t)rb * FDIM + col) = vb;
    }
}

// fused: g2 = relu(Bv Wg2 + b_g2) in registers; out = L Wf_top + g2 Wf_bot + b_fuse
__global__ void __launch_bounds__(256)
k_fuse2(const float* __restrict__ Bv, const float* __restrict__ L,
        const uint4* __restrict__ Fg2, const uint4* __restrict__ Ftop,
        const uint4* __restrict__ Fbot,
        const float* __restrict__ bias_g2, const float* __restrict__ bias_f,
        float* __restrict__ out, int M) {
    int lane = threadIdx.x & 31, warp = threadIdx.x >> 5;
    int row0 = blockIdx.x * 128 + warp * 16;
    int r  = lane >> 2;
    int cq = (lane & 3) * 2;
    int ra = row0 + r, rb = row0 + r + 8;

    // phase 1: g2 accumulators
    float g2[12][4];
    #pragma unroll
    for (int nt = 0; nt < 12; nt++)
        #pragma unroll
        for (int j = 0; j < 4; j++) g2[nt][j] = 0.f;
    gemm_chunk(Bv, Fg2, row0, lane, M, g2);
    #pragma unroll
    for (int nt = 0; nt < 12; nt++) {
        int col = nt * 8 + cq;
        float2 bb = *reinterpret_cast<const float2*>(bias_g2 + col);
        g2[nt][0] = fmaxf(g2[nt][0] + bb.x, 0.f);
        g2[nt][1] = fmaxf(g2[nt][1] + bb.y, 0.f);
        g2[nt][2] = fmaxf(g2[nt][2] + bb.x, 0.f);
        g2[nt][3] = fmaxf(g2[nt][3] + bb.y, 0.f);
    }

    // phase 2: out = L @ Wf_top
    float acc[12][4];
    #pragma unroll
    for (int nt = 0; nt < 12; nt++)
        #pragma unroll
        for (int j = 0; j < 4; j++) acc[nt][j] = 0.f;
    gemm_chunk(L, Ftop, row0, lane, M, acc);

    // phase 3: out += g2 @ Wf_bot (C-frag of g2 reinterpreted as A-frags)
    #pragma unroll
    for (int kt = 0; kt < 6; kt++) {
        uint32_t ah[4] = { pack_hi2(g2[2*kt][0],   g2[2*kt][1]),
                           pack_hi2(g2[2*kt][2],   g2[2*kt][3]),
                           pack_hi2(g2[2*kt+1][0], g2[2*kt+1][1]),
                           pack_hi2(g2[2*kt+1][2], g2[2*kt+1][3]) };
        uint32_t al[4] = { pack_lo2(g2[2*kt][0],   g2[2*kt][1]),
                           pack_lo2(g2[2*kt][2],   g2[2*kt][3]),
                           pack_lo2(g2[2*kt+1][0], g2[2*kt+1][1]),
                           pack_lo2(g2[2*kt+1][2], g2[2*kt+1][3]) };
        const uint4* fp = Fbot + (size_t)kt * 12 * 32 + lane;
        #pragma unroll
        for (int nt = 0; nt < 12; nt++) {
            uint4 b = fp[nt * 32];
            mma16816(acc[nt], ah, b.x, b.y);
            mma16816(acc[nt], ah, b.z, b.w);
            mma16816(acc[nt], al, b.x, b.y);
        }
    }

    #pragma unroll
    for (int nt = 0; nt < 12; nt++) {
        int col = nt * 8 + cq;
        float2 bb = *reinterpret_cast<const float2*>(bias_f + col);
        float2 va = make_float2(acc[nt][0] + bb.x, acc[nt][1] + bb.y);
        float2 vb = make_float2(acc[nt][2] + bb.x, acc[nt][3] + bb.y);
        if (ra < M) *reinterpret_cast<float2*>(out + (size_t)ra * FDIM + col) = va;
        if (rb < M) *reinterpret_cast<float2*>(out + (size_t)rb * FDIM + col) = vb;
    }
}

// ---------------- launch ----------------
extern "C" void kernel_launch(void* const* d_in, const int* in_sizes, int n_in,
                              void* d_out, int out_size) {
    const float* x       = (const float*)d_in[0];
    const int*   ei      = (const int*)  d_in[1];
    const float* W_local = (const float*)d_in[2];
    const float* b_local = (const float*)d_in[3];
    const float* W_g1    = (const float*)d_in[4];
    const float* b_g1    = (const float*)d_in[5];
    const float* W_g2    = (const float*)d_in[6];
    const float* b_g2    = (const float*)d_in[7];
    const float* W_fuse  = (const float*)d_in[8];
    const float* b_fuse  = (const float*)d_in[9];
    float* out = (float*)d_out;

    int n = in_sizes[0] / FDIM; if (n > NMAX) n = NMAX;
    int e = in_sizes[1] / 2;    if (e > EMAX) e = EMAX;

    float *pXs, *pA, *pG1, *pBv, *pL;
    uint4* pF;
    cudaGetSymbolAddress((void**)&pXs, g_Xs);
    cudaGetSymbolAddress((void**)&pA,  g_A);
    cudaGetSymbolAddress((void**)&pG1, g_G1);
    cudaGetSymbolAddress((void**)&pBv, g_Bv);
    cudaGetSymbolAddress((void**)&pL,  g_L);
    cudaGetSymbolAddress((void**)&pF,  g_frag);

    const int tb = 256;
    int eq = (e + 3) / 4;
    k_zero <<<(n + tb - 1) / tb, tb>>>(n);
    k_fill <<<(eq + tb - 1) / tb, tb>>>(ei, e);
    k_dis  <<<(n + tb - 1) / tb, tb>>>(n);
    k_scale<<<(n * 24 + tb - 1) / tb, tb>>>(x, n);
    k_prepB<<<(5 * FRAG_PER_IMG + tb - 1) / tb, tb>>>(W_local, W_g1, W_g2, W_fuse);

    int aggGrid = (n + 7) / 8;
    int gGrid   = (n + 127) / 128;

    // A = P x  (from prescaled x')
    k_agg<<<aggGrid, 256>>>(pXs, pA, n);
    // local = relu(A Wl + b); g1' = dis * relu(A Wg1 + b)
    k_dualgemm<<<gGrid, 256>>>(pA, pF + 0 * FRAG_PER_IMG, pF + 1 * FRAG_PER_IMG,
                               b_local, b_g1, pL, pG1, n);
    // Bv = P g1  (from prescaled g1')
    k_agg<<<aggGrid, 256>>>(pG1, pBv, n);
    // out = L Wf_top + relu(Bv Wg2 + b) Wf_bot + b_fuse
    k_fuse2<<<gGrid, 256>>>(pBv, pL,
                            pF + 2 * FRAG_PER_IMG, pF + 3 * FRAG_PER_IMG, pF + 4 * FRAG_PER_IMG,
                            b_g2, b_fuse, out, n);
}

// round 8
// speedup vs baseline: 1.3585x; 1.0232x over previous
#include <cuda_runtime.h>
#include <cuda_bf16.h>
#include <cstdint>

#define NMAX 50000
#define EMAX 800000
#define FDIM 96
#define DEG_PAD 128
#define PROW 48   // packed uint2 (hi-pair, lo-pair) per row

// ---------------- scratch (device globals: allocation-free) ----------------
__device__ int   g_deg[NMAX];
__device__ float g_dis[NMAX];
__device__ __align__(16) int   g_ell[(size_t)NMAX * DEG_PAD];
__device__ __align__(16) float g_Xs[(size_t)NMAX * FDIM];    // dis * x
__device__ __align__(16) float g_G1[(size_t)NMAX * FDIM];    // dis * relu(A W_g1 + b)
__device__ __align__(16) uint2 g_Ap [(size_t)NMAX * PROW];   // packed P x
__device__ __align__(16) uint2 g_Lp [(size_t)NMAX * PROW];   // packed local
__device__ __align__(16) uint2 g_Bvp[(size_t)NMAX * PROW];   // packed P g1
// precomputed B fragments in mma-lane layout: [img][kt<6][nt<12][lane<32]
// uint4 = {b_hi reg0, b_hi reg1, b_lo reg0, b_lo reg1}
#define FRAG_PER_IMG (6 * 12 * 32)
__device__ __align__(16) uint4 g_frag[5 * FRAG_PER_IMG];

// ---------------- bf16 hi/lo packing helpers ----------------
__device__ __forceinline__ uint32_t pack_hi2(float a, float b) {
    __nv_bfloat162 h = __floats2bfloat162_rn(a, b);
    return *reinterpret_cast<uint32_t*>(&h);
}
__device__ __forceinline__ uint32_t pack_lo2(float a, float b) {
    __nv_bfloat162 h = __floats2bfloat162_rn(a, b);
    float2 f = __bfloat1622float2(h);
    __nv_bfloat162 l = __floats2bfloat162_rn(a - f.x, b - f.y);
    return *reinterpret_cast<uint32_t*>(&l);
}

// ---------------- degree / ELL build ----------------
__global__ void k_zero(int n) {
    int i = blockIdx.x * blockDim.x + threadIdx.x;
    if (i < n) g_deg[i] = 0;
}
__global__ void k_fill(const int* __restrict__ ei, int e_cnt) {
    int i = blockIdx.x * blockDim.x + threadIdx.x;
    int e0 = i * 4;
    if (e0 + 3 < e_cnt) {
        int4 s = *reinterpret_cast<const int4*>(ei + e0);
        int4 d = *reinterpret_cast<const int4*>(ei + e_cnt + e0);
        int p;
        p = atomicAdd(&g_deg[d.x], 1); if (p < DEG_PAD) g_ell[(size_t)d.x * DEG_PAD + p] = s.x;
        p = atomicAdd(&g_deg[d.y], 1); if (p < DEG_PAD) g_ell[(size_t)d.y * DEG_PAD + p] = s.y;
        p = atomicAdd(&g_deg[d.z], 1); if (p < DEG_PAD) g_ell[(size_t)d.z * DEG_PAD + p] = s.z;
        p = atomicAdd(&g_deg[d.w], 1); if (p < DEG_PAD) g_ell[(size_t)d.w * DEG_PAD + p] = s.w;
    } else {
        for (int e = e0; e < e_cnt && e < e0 + 4; e++) {
            int s = ei[e], d = ei[e_cnt + e];
            int p = atomicAdd(&g_deg[d], 1);
            if (p < DEG_PAD) g_ell[(size_t)d * DEG_PAD + p] = s;
        }
    }
}
__global__ void k_dis(int n) {
    int i = blockIdx.x * blockDim.x + threadIdx.x;
    if (i < n) g_dis[i] = rsqrtf((float)(g_deg[i] + 1));
}
// x' = dis * x
__global__ void k_scale(const float* __restrict__ x, int n) {
    int i = blockIdx.x * blockDim.x + threadIdx.x;
    if (i >= n * 24) return;
    int row = i / 24, c4 = (i % 24) * 4;
    float d = g_dis[row];
    float4 v = *reinterpret_cast<const float4*>(x + (size_t)row * FDIM + c4);
    v.x *= d; v.y *= d; v.z *= d; v.w *= d;
    *reinterpret_cast<float4*>(g_Xs + (size_t)row * FDIM + c4) = v;
}

// ---------------- weight prep: B fragments ----------------
__global__ void k_prepB(const float* __restrict__ Wl, const float* __restrict__ Wg1,
                        const float* __restrict__ Wg2, const float* __restrict__ Wf) {
    int i = blockIdx.x * blockDim.x + threadIdx.x;
    if (i >= 5 * FRAG_PER_IMG) return;
    int lane = i & 31;
    int nt   = (i >> 5) % 12;
    int kt   = ((i >> 5) / 12) % 6;
    int img  = i / FRAG_PER_IMG;

    int n  = nt * 8 + (lane >> 2);
    int k0 = kt * 16 + (lane & 3) * 2;

    const float* W;
    int koff = 0;
    if      (img == 0) W = Wl;
    else if (img == 1) W = Wg1;
    else if (img == 2) W = Wg2;
    else if (img == 3) W = Wf;
    else               { W = Wf; koff = 96; }

    float w0 = W[(size_t)(koff + k0)     * 96 + n];
    float w1 = W[(size_t)(koff + k0 + 1) * 96 + n];
    float w8 = W[(size_t)(koff + k0 + 8) * 96 + n];
    float w9 = W[(size_t)(koff + k0 + 9) * 96 + n];

    uint4 o;
    o.x = pack_hi2(w0, w1);
    o.y = pack_hi2(w8, w9);
    o.z = pack_lo2(w0, w1);
    o.w = pack_lo2(w8, w9);
    g_frag[i] = o;
}

// ---------------- aggregation: packed-output
// out_packed[i] = pack( dis[i]*( sum_src h'[src] + h'[i] ) )
__global__ void __launch_bounds__(256) k_agg(const float* __restrict__ h,
                                             uint2* __restrict__ Pout, int n) {
    int warp = blockIdx.x * 8 + (threadIdx.x >> 5);
    int lane = threadIdx.x & 31;
    if (warp >= n) return;

    int cnt = g_deg[warp];
    cnt = cnt < DEG_PAD ? cnt : DEG_PAD;
    float di = g_dis[warp];
    const int* row = g_ell + (size_t)warp * DEG_PAD;

    const float* hs = h + (size_t)warp * FDIM;   // self term (already scaled)
    float a0 = hs[lane];
    float a1 = hs[lane + 32];
    float a2 = hs[lane + 64];

    for (int base = 0; base < cnt; base += 32) {
        int take = cnt - base; if (take > 32) take = 32;
        int s = 0;
        if (lane < take) s = row[base + lane];
        #pragma unroll 8
        for (int j = 0; j < take; j++) {
            int ss = __shfl_sync(0xffffffffu, s, j);
            const float* hp = h + (size_t)ss * FDIM;
            a0 += hp[lane];
            a1 += hp[lane + 32];
            a2 += hp[lane + 64];
        }
    }
    float v0 = di * a0, v1 = di * a1, v2 = di * a2;
    float n0 = __shfl_xor_sync(0xffffffffu, v0, 1);
    float n1 = __shfl_xor_sync(0xffffffffu, v1, 1);
    float n2 = __shfl_xor_sync(0xffffffffu, v2, 1);
    if ((lane & 1) == 0) {
        int c = lane >> 1;   // 0..15
        uint2* P = Pout + (size_t)warp * PROW;
        P[c]      = make_uint2(pack_hi2(v0, n0), pack_lo2(v0, n0));
        P[16 + c] = make_uint2(pack_hi2(v1, n1), pack_lo2(v1, n1));
        P[32 + c] = make_uint2(pack_hi2(v2, n2), pack_lo2(v2, n2));
    }
}

// ---------------- mma.sync bf16 GEMM (HMMA path, portable PTX) ----------------
__device__ __forceinline__ void mma16816(float acc[4], const uint32_t a[4],
                                         uint32_t b0, uint32_t b1) {
    asm volatile(
        "mma.sync.aligned.m16n8k16.row.col.f32.bf16.bf16.f32 "
        "{%0,%1,%2,%3}, {%4,%5,%6,%7}, {%8,%9}, {%0,%1,%2,%3};"
        : "+f"(acc[0]), "+f"(acc[1]), "+f"(acc[2]), "+f"(acc[3])
        : "r"(a[0]), "r"(a[1]), "r"(a[2]), "r"(a[3]), "r"(b0), "r"(b1));
}

// load pre-packed a-frags for one kt: 4 LDG.64, zero ALU
__device__ __forceinline__ void load_afrag(const uint2* __restrict__ P,
                                           int ra, int rb, int M, int kt, int lane,
                                           uint32_t ah[4], uint32_t al[4]) {
    const uint2 z2 = make_uint2(0u, 0u);
    int c0 = kt * 8 + (lane & 3);
    uint2 p0 = (ra < M) ? P[(size_t)ra * PROW + c0]     : z2;
    uint2 p1 = (rb < M) ? P[(size_t)rb * PROW + c0]     : z2;
    uint2 p2 = (ra < M) ? P[(size_t)ra * PROW + c0 + 4] : z2;
    uint2 p3 = (rb < M) ? P[(size_t)rb * PROW + c0 + 4] : z2;
    ah[0] = p0.x; ah[1] = p1.x; ah[2] = p2.x; ah[3] = p3.x;
    al[0] = p0.y; al[1] = p1.y; al[2] = p2.y; al[3] = p3.y;
}

// one K=96 chunk into acc from packed input
__device__ __forceinline__ void gemm_chunk(const uint2* __restrict__ P,
                                           const uint4* __restrict__ F,
                                           int row0, int lane, int M,
                                           float acc[12][4]) {
    int r  = lane >> 2;
    int ra = row0 + r, rb = row0 + r + 8;
    #pragma unroll
    for (int kt = 0; kt < 6; kt++) {
        uint32_t ah[4], al[4];
        load_afrag(P, ra, rb, M, kt, lane, ah, al);
        const uint4* fp = F + (size_t)kt * 12 * 32 + lane;
        #pragma unroll
        for (int nt = 0; nt < 12; nt++) {
            uint4 b = fp[nt * 32];
            mma16816(acc[nt], ah, b.x, b.y);   // hi*hi
            mma16816(acc[nt], ah, b.z, b.w);   // hi*lo
            mma16816(acc[nt], al, b.x, b.y);   // lo*hi
        }
    }
}

// dual-output GEMM sharing packed input A:
//   Lp = pack(relu(A W1 + b1));  G1 = dis * relu(A W2 + b2)  (fp32)
__global__ void __launch_bounds__(256)
k_dualgemm(const uint2* __restrict__ P,
           const uint4* __restrict__ F1, const uint4* __restrict__ F2,
           const float* __restrict__ bias1, const float* __restrict__ bias2,
           uint2* __restrict__ Lp, float* __restrict__ G1, int M) {
    int lane = threadIdx.x & 31, warp = threadIdx.x >> 5;
    int row0 = blockIdx.x * 128 + warp * 16;
    int r  = lane >> 2;
    int cq = (lane & 3) * 2;
    int ra = row0 + r, rb = row0 + r + 8;

    float acc1[12][4], acc2[12][4];
    #pragma unroll
    for (int nt = 0; nt < 12; nt++)
        #pragma unroll
        for (int j = 0; j < 4; j++) { acc1[nt][j] = 0.f; acc2[nt][j] = 0.f; }

    #pragma unroll
    for (int kt = 0; kt < 6; kt++) {
        uint32_t ah[4], al[4];
        load_afrag(P, ra, rb, M, kt, lane, ah, al);
        const uint4* fp1 = F1 + (size_t)kt * 12 * 32 + lane;
        const uint4* fp2 = F2 + (size_t)kt * 12 * 32 + lane;
        #pragma unroll
        for (int nt = 0; nt < 12; nt++) {
            uint4 b1 = fp1[nt * 32];
            mma16816(acc1[nt], ah, b1.x, b1.y);
            mma16816(acc1[nt], ah, b1.z, b1.w);
            mma16816(acc1[nt], al, b1.x, b1.y);
            uint4 b2 = fp2[nt * 32];
            mma16816(acc2[nt], ah, b2.x, b2.y);
            mma16816(acc2[nt], ah, b2.z, b2.w);
            mma16816(acc2[nt], al, b2.x, b2.y);
        }
    }

    float da = (ra < M) ? g_dis[ra] : 0.f;
    float db = (rb < M) ? g_dis[rb] : 0.f;
    #pragma unroll
    for (int nt = 0; nt < 12; nt++) {
        int col = nt * 8 + cq;
        int cpi = col >> 1;                       // packed pair index
        float2 bb1 = *reinterpret_cast<const float2*>(bias1 + col);
        float2 bb2 = *reinterpret_cast<const float2*>(bias2 + col);
        // local -> packed
        float lx = fmaxf(acc1[nt][0] + bb1.x, 0.f), ly = fmaxf(acc1[nt][1] + bb1.y, 0.f);
        float mx = fmaxf(acc1[nt][2] + bb1.x, 0.f), my = fmaxf(acc1[nt][3] + bb1.y, 0.f);
        if (ra < M) Lp[(size_t)ra * PROW + cpi] = make_uint2(pack_hi2(lx, ly), pack_lo2(lx, ly));
        if (rb < M) Lp[(size_t)rb * PROW + cpi] = make_uint2(pack_hi2(mx, my), pack_lo2(mx, my));
        // g1' -> fp32
        float2 va = make_float2(da * fmaxf(acc2[nt][0] + bb2.x, 0.f),
                                da * fmaxf(acc2[nt][1] + bb2.y, 0.f));
        float2 vb = make_float2(db * fmaxf(acc2[nt][2] + bb2.x, 0.f),
                                db * fmaxf(acc2[nt][3] + bb2.y, 0.f));
        if (ra < M) *reinterpret_cast<float2*>(G1 + (size_t)ra * FDIM + col) = va;
        if (rb < M) *reinterpret_cast<float2*>(G1 + (size_t)rb * FDIM + col) = vb;
    }
}

// fused: g2 = relu(Bv Wg2 + b_g2) in registers; out = L Wf_top + g2 Wf_bot + b_fuse
__global__ void __launch_bounds__(256)
k_fuse2(const uint2* __restrict__ Bvp, const uint2* __restrict__ Lp,
        const uint4* __restrict__ Fg2, const uint4* __restrict__ Ftop,
        const uint4* __restrict__ Fbot,
        const float* __restrict__ bias_g2, const float* __restrict__ bias_f,
        float* __restrict__ out, int M) {
    int lane = threadIdx.x & 31, warp = threadIdx.x >> 5;
    int row0 = blockIdx.x * 128 + warp * 16;
    int r  = lane >> 2;
    int cq = (lane & 3) * 2;
    int ra = row0 + r, rb = row0 + r + 8;

    // phase 1: g2 accumulators
    float g2[12][4];
    #pragma unroll
    for (int nt = 0; nt < 12; nt++)
        #pragma unroll
        for (int j = 0; j < 4; j++) g2[nt][j] = 0.f;
    gemm_chunk(Bvp, Fg2, row0, lane, M, g2);
    #pragma unroll
    for (int nt = 0; nt < 12; nt++) {
        int col = nt * 8 + cq;
        float2 bb = *reinterpret_cast<const float2*>(bias_g2 + col);
        g2[nt][0] = fmaxf(g2[nt][0] + bb.x, 0.f);
        g2[nt][1] = fmaxf(g2[nt][1] + bb.y, 0.f);
        g2[nt][2] = fmaxf(g2[nt][2] + bb.x, 0.f);
        g2[nt][3] = fmaxf(g2[nt][3] + bb.y, 0.f);
    }

    // phase 2: out = L @ Wf_top
    float acc[12][4];
    #pragma unroll
    for (int nt = 0; nt < 12; nt++)
        #pragma unroll
        for (int j = 0; j < 4; j++) acc[nt][j] = 0.f;
    gemm_chunk(Lp, Ftop, row0, lane, M, acc);

    // phase 3: out += g2 @ Wf_bot (C-frag of g2 reinterpreted as A-frags)
    #pragma unroll
    for (int kt = 0; kt < 6; kt++) {
        uint32_t ah[4] = { pack_hi2(g2[2*kt][0],   g2[2*kt][1]),
                           pack_hi2(g2[2*kt][2],   g2[2*kt][3]),
                           pack_hi2(g2[2*kt+1][0], g2[2*kt+1][1]),
                           pack_hi2(g2[2*kt+1][2], g2[2*kt+1][3]) };
        uint32_t al[4] = { pack_lo2(g2[2*kt][0],   g2[2*kt][1]),
                           pack_lo2(g2[2*kt][2],   g2[2*kt][3]),
                           pack_lo2(g2[2*kt+1][0], g2[2*kt+1][1]),
                           pack_lo2(g2[2*kt+1][2], g2[2*kt+1][3]) };
        const uint4* fp = Fbot + (size_t)kt * 12 * 32 + lane;
        #pragma unroll
        for (int nt = 0; nt < 12; nt++) {
            uint4 b = fp[nt * 32];
            mma16816(acc[nt], ah, b.x, b.y);
            mma16816(acc[nt], ah, b.z, b.w);
            mma16816(acc[nt], al, b.x, b.y);
        }
    }

    #pragma unroll
    for (int nt = 0; nt < 12; nt++) {
        int col = nt * 8 + cq;
        float2 bb = *reinterpret_cast<const float2*>(bias_f + col);
        float2 va = make_float2(acc[nt][0] + bb.x, acc[nt][1] + bb.y);
        float2 vb = make_float2(acc[nt][2] + bb.x, acc[nt][3] + bb.y);
        if (ra < M) *reinterpret_cast<float2*>(out + (size_t)ra * FDIM + col) = va;
        if (rb < M) *reinterpret_cast<float2*>(out + (size_t)rb * FDIM + col) = vb;
    }
}

// ---------------- launch ----------------
extern "C" void kernel_launch(void* const* d_in, const int* in_sizes, int n_in,
                              void* d_out, int out_size) {
    const float* x       = (const float*)d_in[0];
    const int*   ei      = (const int*)  d_in[1];
    const float* W_local = (const float*)d_in[2];
    const float* b_local = (const float*)d_in[3];
    const float* W_g1    = (const float*)d_in[4];
    const float* b_g1    = (const float*)d_in[5];
    const float* W_g2    = (const float*)d_in[6];
    const float* b_g2    = (const float*)d_in[7];
    const float* W_fuse  = (const float*)d_in[8];
    const float* b_fuse  = (const float*)d_in[9];
    float* out = (float*)d_out;

    int n = in_sizes[0] / FDIM; if (n > NMAX) n = NMAX;
    int e = in_sizes[1] / 2;    if (e > EMAX) e = EMAX;

    float *pXs, *pG1;
    uint2 *pAp, *pLp, *pBvp;
    uint4* pF;
    cudaGetSymbolAddress((void**)&pXs,  g_Xs);
    cudaGetSymbolAddress((void**)&pG1,  g_G1);
    cudaGetSymbolAddress((void**)&pAp,  g_Ap);
    cudaGetSymbolAddress((void**)&pLp,  g_Lp);
    cudaGetSymbolAddress((void**)&pBvp, g_Bvp);
    cudaGetSymbolAddress((void**)&pF,   g_frag);

    const int tb = 256;
    int eq = (e + 3) / 4;
    k_zero <<<(n + tb - 1) / tb, tb>>>(n);
    k_fill <<<(eq + tb - 1) / tb, tb>>>(ei, e);
    k_dis  <<<(n + tb - 1) / tb, tb>>>(n);
    k_scale<<<(n * 24 + tb - 1) / tb, tb>>>(x, n);
    k_prepB<<<(5 * FRAG_PER_IMG + tb - 1) / tb, tb>>>(W_local, W_g1, W_g2, W_fuse);

    int aggGrid = (n + 7) / 8;
    int gGrid   = (n + 127) / 128;

    // Ap = pack(P x)
    k_agg<<<aggGrid, 256>>>(pXs, pAp, n);
    // Lp = pack(relu(A Wl + b)); g1' = dis * relu(A Wg1 + b)
    k_dualgemm<<<gGrid, 256>>>(pAp, pF + 0 * FRAG_PER_IMG, pF + 1 * FRAG_PER_IMG,
                               b_local, b_g1, pLp, pG1, n);
    // Bvp = pack(P g1)
    k_agg<<<aggGrid, 256>>>(pG1, pBvp, n);
    // out = L Wf_top + relu(Bv Wg2 + b) Wf_bot + b_fuse
    k_fuse2<<<gGrid, 256>>>(pBvp, pLp,
                            pF + 2 * FRAG_PER_IMG, pF + 3 * FRAG_PER_IMG, pF + 4 * FRAG_PER_IMG,
                            b_g2, b_fuse, out, n);
}

// round 11
// speedup vs baseline: 1.3693x; 1.0080x over previous
#include <cuda_runtime.h>
#include <cuda_bf16.h>
#include <cuda_fp16.h>
#include <cstdint>

#define NMAX 50000
#define EMAX 800000
#define FDIM 96
#define DEG_PAD 128
#define PROW 48   // packed uint2 (hi-pair, lo-pair) per row
#define HROW 48   // half2 per row

// ---------------- scratch (device globals: allocation-free) ----------------
__device__ int   g_deg[NMAX];
__device__ float g_dis[NMAX];
__device__ __align__(16) int     g_ell[(size_t)NMAX * DEG_PAD];
__device__ __align__(16) __half2 g_Xh [(size_t)NMAX * HROW];   // half2( dis * x )
__device__ __align__(16) __half2 g_G1h[(size_t)NMAX * HROW];   // half2( dis * relu(A Wg1 + b) )
__device__ __align__(16) uint2   g_Ap [(size_t)NMAX * PROW];   // packed P x
__device__ __align__(16) uint2   g_Lp [(size_t)NMAX * PROW];   // packed local
__device__ __align__(16) uint2   g_Bvp[(size_t)NMAX * PROW];   // packed P g1
// precomputed B fragments in mma-lane layout: [img][kt<6][nt<12][lane<32]
#define FRAG_PER_IMG (6 * 12 * 32)
__device__ __align__(16) uint4 g_frag[5 * FRAG_PER_IMG];

// ---------------- bf16 hi/lo packing helpers ----------------
__device__ __forceinline__ uint32_t pack_hi2(float a, float b) {
    __nv_bfloat162 h = __floats2bfloat162_rn(a, b);
    return *reinterpret_cast<uint32_t*>(&h);
}
__device__ __forceinline__ uint32_t pack_lo2(float a, float b) {
    __nv_bfloat162 h = __floats2bfloat162_rn(a, b);
    float2 f = __bfloat1622float2(h);
    __nv_bfloat162 l = __floats2bfloat162_rn(a - f.x, b - f.y);
    return *reinterpret_cast<uint32_t*>(&l);
}

// ---------------- weight prep (also zeroes g_deg) ----------------
__global__ void k_prepB(const float* __restrict__ Wl, const float* __restrict__ Wg1,
                        const float* __restrict__ Wg2, const float* __restrict__ Wf,
                        int n) {
    int i = blockIdx.x * blockDim.x + threadIdx.x;
    if (i < n) g_deg[i] = 0;
    if (i >= 5 * FRAG_PER_IMG) return;
    int lane = i & 31;
    int nt   = (i >> 5) % 12;
    int kt   = ((i >> 5) / 12) % 6;
    int img  = i / FRAG_PER_IMG;

    int nn = nt * 8 + (lane >> 2);
    int k0 = kt * 16 + (lane & 3) * 2;

    const float* W;
    int koff = 0;
    if      (img == 0) W = Wl;
    else if (img == 1) W = Wg1;
    else if (img == 2) W = Wg2;
    else if (img == 3) W = Wf;
    else               { W = Wf; koff = 96; }

    float w0 = W[(size_t)(koff + k0)     * 96 + nn];
    float w1 = W[(size_t)(koff + k0 + 1) * 96 + nn];
    float w8 = W[(size_t)(koff + k0 + 8) * 96 + nn];
    float w9 = W[(size_t)(koff + k0 + 9) * 96 + nn];

    uint4 o;
    o.x = pack_hi2(w0, w1);
    o.y = pack_hi2(w8, w9);
    o.z = pack_lo2(w0, w1);
    o.w = pack_lo2(w8, w9);
    g_frag[i] = o;
}

// ---------------- degree / ELL build ----------------
__global__ void k_fill(const int* __restrict__ ei, int e_cnt) {
    int i = blockIdx.x * blockDim.x + threadIdx.x;
    int e0 = i * 4;
    if (e0 + 3 < e_cnt) {
        int4 s = *reinterpret_cast<const int4*>(ei + e0);
        int4 d = *reinterpret_cast<const int4*>(ei + e_cnt + e0);
        int p;
        p = atomicAdd(&g_deg[d.x], 1); if (p < DEG_PAD) g_ell[(size_t)d.x * DEG_PAD + p] = s.x;
        p = atomicAdd(&g_deg[d.y], 1); if (p < DEG_PAD) g_ell[(size_t)d.y * DEG_PAD + p] = s.y;
        p = atomicAdd(&g_deg[d.z], 1); if (p < DEG_PAD) g_ell[(size_t)d.z * DEG_PAD + p] = s.z;
        p = atomicAdd(&g_deg[d.w], 1); if (p < DEG_PAD) g_ell[(size_t)d.w * DEG_PAD + p] = s.w;
    } else {
        for (int e = e0; e < e_cnt && e < e0 + 4; e++) {
            int s = ei[e], d = ei[e_cnt + e];
            int p = atomicAdd(&g_deg[d], 1);
            if (p < DEG_PAD) g_ell[(size_t)d * DEG_PAD + p] = s;
        }
    }
}
__global__ void k_dis(int n) {
    int i = blockIdx.x * blockDim.x + threadIdx.x;
    if (i < n) g_dis[i] = rsqrtf((float)(g_deg[i] + 1));
}
// Xh = half2( dis * x )
__global__ void k_toH(const float* __restrict__ x, int n) {
    int i = blockIdx.x * blockDim.x + threadIdx.x;
    if (i >= n * HROW) return;
    int row = i / HROW, p = i % HROW;
    float d = g_dis[row];
    float2 v = *reinterpret_cast<const float2*>(x + (size_t)row * FDIM + p * 2);
    g_Xh[(size_t)row * HROW + p] = __floats2half2_rn(d * v.x, d * v.y);
}

// ---------------- aggregation: fp16 gather, fp32 accumulate, packed bf16 hi/lo out
// Pout[i] = pack( dis[i] * ( sum_src h[src] + h[i] ) ), h prescaled fp16
__global__ void __launch_bounds__(256) k_agg(const __half2* __restrict__ h,
                                             uint2* __restrict__ Pout, int n) {
    int warp = blockIdx.x * 8 + (threadIdx.x >> 5);
    int lane = threadIdx.x & 31;
    if (warp >= n) return;

    int cnt = g_deg[warp];
    cnt = cnt < DEG_PAD ? cnt : DEG_PAD;
    float di = g_dis[warp];
    const int* row = g_ell + (size_t)warp * DEG_PAD;

    // lane l owns cols (2l, 2l+1); lanes 0..15 also own cols (64+2l, 65+2l)
    const __half2* hs = h + (size_t)warp * HROW;
    float2 f = __half22float2(hs[lane]);
    float a0 = f.x, a1 = f.y;
    float a2 = 0.f, a3 = 0.f;
    if (lane < 16) {
        float2 g = __half22float2(hs[32 + lane]);
        a2 = g.x; a3 = g.y;
    }

    for (int base = 0; base < cnt; base += 32) {
        int take = cnt - base; if (take > 32) take = 32;
        int s = 0;
        if (lane < take) s = row[base + lane];
        #pragma unroll 8
        for (int j = 0; j < take; j++) {
            int ss = __shfl_sync(0xffffffffu, s, j);
            const __half2* hp = h + (size_t)ss * HROW;
            float2 u = __half22float2(hp[lane]);
            a0 += u.x; a1 += u.y;
            if (lane < 16) {
                float2 w = __half22float2(hp[32 + lane]);
                a2 += w.x; a3 += w.y;
            }
        }
    }
    a0 *= di; a1 *= di; a2 *= di; a3 *= di;
    uint2* P = Pout + (size_t)warp * PROW;
    P[lane] = make_uint2(pack_hi2(a0, a1), pack_lo2(a0, a1));
    if (lane < 16)
        P[32 + lane] = make_uint2(pack_hi2(a2, a3), pack_lo2(a2, a3));
}

// ---------------- mma.sync bf16 GEMM (HMMA path, portable PTX) ----------------
__device__ __forceinline__ void mma16816(float acc[4], const uint32_t a[4],
                                         uint32_t b0, uint32_t b1) {
    asm volatile(
        "mma.sync.aligned.m16n8k16.row.col.f32.bf16.bf16.f32 "
        "{%0,%1,%2,%3}, {%4,%5,%6,%7}, {%8,%9}, {%0,%1,%2,%3};"
        : "+f"(acc[0]), "+f"(acc[1]), "+f"(acc[2]), "+f"(acc[3])
        : "r"(a[0]), "r"(a[1]), "r"(a[2]), "r"(a[3]), "r"(b0), "r"(b1));
}

// load pre-packed a-frags for one kt: 4 LDG.64, zero ALU
__device__ __forceinline__ void load_afrag(const uint2* __restrict__ P,
                                           int ra, int rb, int M, int kt, int lane,
                                           uint32_t ah[4], uint32_t al[4]) {
    const uint2 z2 = make_uint2(0u, 0u);
    int c0 = kt * 8 + (lane & 3);
    uint2 p0 = (ra < M) ? P[(size_t)ra * PROW + c0]     : z2;
    uint2 p1 = (rb < M) ? P[(size_t)rb * PROW + c0]     : z2;
    uint2 p2 = (ra < M) ? P[(size_t)ra * PROW + c0 + 4] : z2;
    uint2 p3 = (rb < M) ? P[(size_t)rb * PROW + c0 + 4] : z2;
    ah[0] = p0.x; ah[1] = p1.x; ah[2] = p2.x; ah[3] = p3.x;
    al[0] = p0.y; al[1] = p1.y; al[2] = p2.y; al[3] = p3.y;
}

// one K=96 chunk into acc from packed input
__device__ __forceinline__ void gemm_chunk(const uint2* __restrict__ P,
                                           const uint4* __restrict__ F,
                                           int row0, int lane, int M,
                                           float acc[12][4]) {
    int r  = lane >> 2;
    int ra = row0 + r, rb = row0 + r + 8;
    #pragma unroll
    for (int kt = 0; kt < 6; kt++) {
        uint32_t ah[4], al[4];
        load_afrag(P, ra, rb, M, kt, lane, ah, al);
        const uint4* fp = F + (size_t)kt * 12 * 32 + lane;
        #pragma unroll
        for (int nt = 0; nt < 12; nt++) {
            uint4 b = fp[nt * 32];
            mma16816(acc[nt], ah, b.x, b.y);   // hi*hi
            mma16816(acc[nt], ah, b.z, b.w);   // hi*lo
            mma16816(acc[nt], al, b.x, b.y);   // lo*hi
        }
    }
}

// dual-output GEMM sharing packed input A:
//   Lp = pack(relu(A W1 + b1));  G1h = half2( dis * relu(A W2 + b2) )
__global__ void __launch_bounds__(256)
k_dualgemm(const uint2* __restrict__ P,
           const uint4* __restrict__ F1, const uint4* __restrict__ F2,
           const float* __restrict__ bias1, const float* __restrict__ bias2,
           uint2* __restrict__ Lp, __half2* __restrict__ G1h, int M) {
    int lane = threadIdx.x & 31, warp = threadIdx.x >> 5;
    int row0 = blockIdx.x * 128 + warp * 16;
    int r  = lane >> 2;
    int cq = (lane & 3) * 2;
    int ra = row0 + r, rb = row0 + r + 8;

    float acc1[12][4], acc2[12][4];
    #pragma unroll
    for (int nt = 0; nt < 12; nt++)
        #pragma unroll
        for (int j = 0; j < 4; j++) { acc1[nt][j] = 0.f; acc2[nt][j] = 0.f; }

    #pragma unroll
    for (int kt = 0; kt < 6; kt++) {
        uint32_t ah[4], al[4];
        load_afrag(P, ra, rb, M, kt, lane, ah, al);
        const uint4* fp1 = F1 + (size_t)kt * 12 * 32 + lane;
        const uint4* fp2 = F2 + (size_t)kt * 12 * 32 + lane;
        #pragma unroll
        for (int nt = 0; nt < 12; nt++) {
            uint4 b1 = fp1[nt * 32];
            mma16816(acc1[nt], ah, b1.x, b1.y);
            mma16816(acc1[nt], ah, b1.z, b1.w);
            mma16816(acc1[nt], al, b1.x, b1.y);
            uint4 b2 = fp2[nt * 32];
            mma16816(acc2[nt], ah, b2.x, b2.y);
            mma16816(acc2[nt], ah, b2.z, b2.w);
            mma16816(acc2[nt], al, b2.x, b2.y);
        }
    }

    float da = (ra < M) ? g_dis[ra] : 0.f;
    float db = (rb < M) ? g_dis[rb] : 0.f;
    #pragma unroll
    for (int nt = 0; nt < 12; nt++) {
        int col = nt * 8 + cq;
        int cpi = col >> 1;
        float2 bb1 = *reinterpret_cast<const float2*>(bias1 + col);
        float2 bb2 = *reinterpret_cast<const float2*>(bias2 + col);
        // local -> packed bf16 hi/lo
        float lx = fmaxf(acc1[nt][0] + bb1.x, 0.f), ly = fmaxf(acc1[nt][1] + bb1.y, 0.f);
        float mx = fmaxf(acc1[nt][2] + bb1.x, 0.f), my = fmaxf(acc1[nt][3] + bb1.y, 0.f);
        if (ra < M) Lp[(size_t)ra * PROW + cpi] = make_uint2(pack_hi2(lx, ly), pack_lo2(lx, ly));
        if (rb < M) Lp[(size_t)rb * PROW + cpi] = make_uint2(pack_hi2(mx, my), pack_lo2(mx, my));
        // g1' -> fp16
        if (ra < M)
            G1h[(size_t)ra * HROW + cpi] =
                __floats2half2_rn(da * fmaxf(acc2[nt][0] + bb2.x, 0.f),
                                  da * fmaxf(acc2[nt][1] + bb2.y, 0.f));
        if (rb < M)
            G1h[(size_t)rb * HROW + cpi] =
                __floats2half2_rn(db * fmaxf(acc2[nt][2] + bb2.x, 0.f),
                                  db * fmaxf(acc2[nt][3] + bb2.y, 0.f));
    }
}

// fused: g2 = relu(Bv Wg2 + b_g2) in registers; out = L Wf_top + g2 Wf_bot + b_fuse
__global__ void __launch_bounds__(256)
k_fuse2(const uint2* __restrict__ Bvp, const uint2* __restrict__ Lp,
        const uint4* __restrict__ Fg2, const uint4* __restrict__ Ftop,
        const uint4* __restrict__ Fbot,
        const float* __restrict__ bias_g2, const float* __restrict__ bias_f,
        float* __restrict__ out, int M) {
    int lane = threadIdx.x & 31, warp = threadIdx.x >> 5;
    int row0 = blockIdx.x * 128 + warp * 16;
    int r  = lane >> 2;
    int cq = (lane & 3) * 2;
    int ra = row0 + r, rb = row0 + r + 8;

    // phase 1: g2 accumulators
    float g2[12][4];
    #pragma unroll
    for (int nt = 0; nt < 12; nt++)
        #pragma unroll
        for (int j = 0; j < 4; j++) g2[nt][j] = 0.f;
    gemm_chunk(Bvp, Fg2, row0, lane, M, g2);
    #pragma unroll
    for (int nt = 0; nt < 12; nt++) {
        int col = nt * 8 + cq;
        float2 bb = *reinterpret_cast<const float2*>(bias_g2 + col);
        g2[nt][0] = fmaxf(g2[nt][0] + bb.x, 0.f);
        g2[nt][1] = fmaxf(g2[nt][1] + bb.y, 0.f);
        g2[nt][2] = fmaxf(g2[nt][2] + bb.x, 0.f);
        g2[nt][3] = fmaxf(g2[nt][3] + bb.y, 0.f);
    }

    // phase 2: out = L @ Wf_top
    float acc[12][4];
    #pragma unroll
    for (int nt = 0; nt < 12; nt++)
        #pragma unroll
        for (int j = 0; j < 4; j++) acc[nt][j] = 0.f;
    gemm_chunk(Lp, Ftop, row0, lane, M, acc);

    // phase 3: out += g2 @ Wf_bot (C-frag of g2 reinterpreted as A-frags)
    #pragma unroll
    for (int kt = 0; kt < 6; kt++) {
        uint32_t ah[4] = { pack_hi2(g2[2*kt][0],   g2[2*kt][1]),
                           pack_hi2(g2[2*kt][2],   g2[2*kt][3]),
                           pack_hi2(g2[2*kt+1][0], g2[2*kt+1][1]),
                           pack_hi2(g2[2*kt+1][2], g2[2*kt+1][3]) };
        uint32_t al[4] = { pack_lo2(g2[2*kt][0],   g2[2*kt][1]),
                           pack_lo2(g2[2*kt][2],   g2[2*kt][3]),
                           pack_lo2(g2[2*kt+1][0], g2[2*kt+1][1]),
                           pack_lo2(g2[2*kt+1][2], g2[2*kt+1][3]) };
        const uint4* fp = Fbot + (size_t)kt * 12 * 32 + lane;
        #pragma unroll
        for (int nt = 0; nt < 12; nt++) {
            uint4 b = fp[nt * 32];
            mma16816(acc[nt], ah, b.x, b.y);
            mma16816(acc[nt], ah, b.z, b.w);
            mma16816(acc[nt], al, b.x, b.y);
        }
    }

    #pragma unroll
    for (int nt = 0; nt < 12; nt++) {
        int col = nt * 8 + cq;
        float2 bb = *reinterpret_cast<const float2*>(bias_f + col);
        float2 va = make_float2(acc[nt][0] + bb.x, acc[nt][1] + bb.y);
        float2 vb = make_float2(acc[nt][2] + bb.x, acc[nt][3] + bb.y);
        if (ra < M) *reinterpret_cast<float2*>(out + (size_t)ra * FDIM + col) = va;
        if (rb < M) *reinterpret_cast<float2*>(out + (size_t)rb * FDIM + col) = vb;
    }
}

// ---------------- launch ----------------
extern "C" void kernel_launch(void* const* d_in, const int* in_sizes, int n_in,
                              void* d_out, int out_size) {
    const float* x       = (const float*)d_in[0];
    const int*   ei      = (const int*)  d_in[1];
    const float* W_local = (const float*)d_in[2];
    const float* b_local = (const float*)d_in[3];
    const float* W_g1    = (const float*)d_in[4];
    const float* b_g1    = (const float*)d_in[5];
    const float* W_g2    = (const float*)d_in[6];
    const float* b_g2    = (const float*)d_in[7];
    const float* W_fuse  = (const float*)d_in[8];
    const float* b_fuse  = (const float*)d_in[9];
    float* out = (float*)d_out;

    int n = in_sizes[0] / FDIM; if (n > NMAX) n = NMAX;
    int e = in_sizes[1] / 2;    if (e > EMAX) e = EMAX;

    __half2 *pXh, *pG1h;
    uint2 *pAp, *pLp, *pBvp;
    uint4* pF;
    cudaGetSymbolAddress((void**)&pXh,  g_Xh);
    cudaGetSymbolAddress((void**)&pG1h, g_G1h);
    cudaGetSymbolAddress((void**)&pAp,  g_Ap);
    cudaGetSymbolAddress((void**)&pLp,  g_Lp);
    cudaGetSymbolAddress((void**)&pBvp, g_Bvp);
    cudaGetSymbolAddress((void**)&pF,   g_frag);

    const int tb = 256;
    int eq = (e + 3) / 4;
    int prepThreads = (n > 5 * FRAG_PER_IMG) ? n : 5 * FRAG_PER_IMG;
    // prepB also zeroes g_deg — must precede k_fill
    k_prepB<<<(prepThreads + tb - 1) / tb, tb>>>(W_local, W_g1, W_g2, W_fuse, n);
    k_fill <<<(eq + tb - 1) / tb, tb>>>(ei, e);
    k_dis  <<<(n + tb - 1) / tb, tb>>>(n);
    k_toH  <<<(n * HROW + tb - 1) / tb, tb>>>(x, n);

    int aggGrid = (n + 7) / 8;
    int gGrid   = (n + 127) / 128;

    // Ap = pack(P x)
    k_agg<<<aggGrid, 256>>>(pXh, pAp, n);
    // Lp = pack(relu(A Wl + b)); g1' = half(dis * relu(A Wg1 + b))
    k_dualgemm<<<gGrid, 256>>>(pAp, pF + 0 * FRAG_PER_IMG, pF + 1 * FRAG_PER_IMG,
                               b_local, b_g1, pLp, pG1h, n);
    // Bvp = pack(P g1)
    k_agg<<<aggGrid, 256>>>(pG1h, pBvp, n);
    // out = L Wf_top + relu(Bv Wg2 + b) Wf_bot + b_fuse
    k_fuse2<<<gGrid, 256>>>(pBvp, pLp,
                            pF + 2 * FRAG_PER_IMG, pF + 3 * FRAG_PER_IMG, pF + 4 * FRAG_PER_IMG,
                            b_g2, b_fuse, out, n);
}

// round 12
// speedup vs baseline: 2.0306x; 1.4830x over previous
#include <cuda_runtime.h>
#include <cuda_fp16.h>
#include <cstdint>

#define NMAX 50000
#define EMAX 800000
#define FDIM 96
#define DEG_PAD 128
#define HROW 48   // half2 per row

// ---------------- scratch (device globals: allocation-free) ----------------
__device__ int   g_deg[NMAX];
__device__ float g_dis[NMAX];
__device__ __align__(16) int     g_ell[(size_t)NMAX * DEG_PAD];
__device__ __align__(16) __half2 g_Xh [(size_t)NMAX * HROW];   // half2( dis * x )
__device__ __align__(16) __half2 g_G1h[(size_t)NMAX * HROW];   // half2( dis * relu(A Wg1 + b) )
__device__ __align__(16) __half2 g_Ah [(size_t)NMAX * HROW];   // half2( P x )
__device__ __align__(16) __half2 g_Lh [(size_t)NMAX * HROW];   // half2( local )
__device__ __align__(16) __half2 g_Bvh[(size_t)NMAX * HROW];   // half2( P g1 )
// B fragments (fp16 hi/lo) in mma-lane layout: [img][kt<6][nt<12][lane<32]
// uint4 = {bhi(k0,k1), bhi(k8,k9), blo(k0,k1), blo(k8,k9)}
#define FRAG_PER_IMG (6 * 12 * 32)
__device__ __align__(16) uint4 g_frag[5 * FRAG_PER_IMG];

// ---------------- fp16 packing helpers ----------------
__device__ __forceinline__ uint32_t hpack(float a, float b) {
    __half2 h = __floats2half2_rn(a, b);
    return *reinterpret_cast<uint32_t*>(&h);
}
__device__ __forceinline__ uint32_t hpack_lo(float a, float b) {
    __half2 h = __floats2half2_rn(a, b);
    float2 f = __half22float2(h);
    __half2 l = __floats2half2_rn(a - f.x, b - f.y);
    return *reinterpret_cast<uint32_t*>(&l);
}

// ---------------- weight prep (also zeroes g_deg) ----------------
__global__ void k_prepB(const float* __restrict__ Wl, const float* __restrict__ Wg1,
                        const float* __restrict__ Wg2, const float* __restrict__ Wf,
                        int n) {
    int i = blockIdx.x * blockDim.x + threadIdx.x;
    if (i < n) g_deg[i] = 0;
    if (i >= 5 * FRAG_PER_IMG) return;
    int lane = i & 31;
    int nt   = (i >> 5) % 12;
    int kt   = ((i >> 5) / 12) % 6;
    int img  = i / FRAG_PER_IMG;

    int nn = nt * 8 + (lane >> 2);
    int k0 = kt * 16 + (lane & 3) * 2;

    const float* W;
    int koff = 0;
    if      (img == 0) W = Wl;
    else if (img == 1) W = Wg1;
    else if (img == 2) W = Wg2;
    else if (img == 3) W = Wf;
    else               { W = Wf; koff = 96; }

    float w0 = W[(size_t)(koff + k0)     * 96 + nn];
    float w1 = W[(size_t)(koff + k0 + 1) * 96 + nn];
    float w8 = W[(size_t)(koff + k0 + 8) * 96 + nn];
    float w9 = W[(size_t)(koff + k0 + 9) * 96 + nn];

    uint4 o;
    o.x = hpack(w0, w1);
    o.y = hpack(w8, w9);
    o.z = hpack_lo(w0, w1);
    o.w = hpack_lo(w8, w9);
    g_frag[i] = o;
}

// ---------------- degree / ELL build ----------------
__global__ void k_fill(const int* __restrict__ ei, int e_cnt) {
    int i = blockIdx.x * blockDim.x + threadIdx.x;
    int e0 = i * 4;
    if (e0 + 3 < e_cnt) {
        int4 s = *reinterpret_cast<const int4*>(ei + e0);
        int4 d = *reinterpret_cast<const int4*>(ei + e_cnt + e0);
        int p;
        p = atomicAdd(&g_deg[d.x], 1); if (p < DEG_PAD) g_ell[(size_t)d.x * DEG_PAD + p] = s.x;
        p = atomicAdd(&g_deg[d.y], 1); if (p < DEG_PAD) g_ell[(size_t)d.y * DEG_PAD + p] = s.y;
        p = atomicAdd(&g_deg[d.z], 1); if (p < DEG_PAD) g_ell[(size_t)d.z * DEG_PAD + p] = s.z;
        p = atomicAdd(&g_deg[d.w], 1); if (p < DEG_PAD) g_ell[(size_t)d.w * DEG_PAD + p] = s.w;
    } else {
        for (int e = e0; e < e_cnt && e < e0 + 4; e++) {
            int s = ei[e], d = ei[e_cnt + e];
            int p = atomicAdd(&g_deg[d], 1);
            if (p < DEG_PAD) g_ell[(size_t)d * DEG_PAD + p] = s;
        }
    }
}

// Xh = half2( dis * x ); also writes g_dis (folds former k_dis)
__global__ void k_toH(const float* __restrict__ x, int n) {
    int i = blockIdx.x * blockDim.x + threadIdx.x;
    if (i >= n * 24) return;
    int row = i / 24, q = i % 24;
    float d = rsqrtf((float)(g_deg[row] + 1));
    if (q == 0) g_dis[row] = d;
    float4 v = *reinterpret_cast<const float4*>(x + (size_t)row * FDIM + q * 4);
    uint2 o = make_uint2(hpack(d * v.x, d * v.y), hpack(d * v.z, d * v.w));
    *reinterpret_cast<uint2*>(g_Xh + (size_t)row * HROW + q * 2) = o;
}

// ---------------- aggregation: fp16 gather (uint2/lane), fp32 accumulate, fp16 out
// Pout[i] = half2( dis[i] * ( sum_src h[src] + h[i] ) ), h prescaled
__global__ void __launch_bounds__(256) k_agg(const __half2* __restrict__ h,
                                             __half2* __restrict__ Pout, int n) {
    int warp = blockIdx.x * 8 + (threadIdx.x >> 5);
    int lane = threadIdx.x & 31;
    if (warp >= n) return;

    int cnt = g_deg[warp];
    cnt = cnt < DEG_PAD ? cnt : DEG_PAD;
    float di = g_dis[warp];
    const int* row = g_ell + (size_t)warp * DEG_PAD;
    bool act = lane < 24;     // lane owns cols 4l..4l+3 (2 half2 = uint2)

    float a0 = 0.f, a1 = 0.f, a2 = 0.f, a3 = 0.f;
    if (act) {
        uint2 sv = *reinterpret_cast<const uint2*>(h + (size_t)warp * HROW + lane * 2);
        float2 f0 = __half22float2(*reinterpret_cast<__half2*>(&sv.x));
        float2 f1 = __half22float2(*reinterpret_cast<__half2*>(&sv.y));
        a0 = f0.x; a1 = f0.y; a2 = f1.x; a3 = f1.y;
    }

    for (int base = 0; base < cnt; base += 32) {
        int take = cnt - base; if (take > 32) take = 32;
        int s = 0;
        if (lane < take) s = row[base + lane];
        #pragma unroll 8
        for (int j = 0; j < take; j++) {
            int ss = __shfl_sync(0xffffffffu, s, j);
            if (act) {
                uint2 u = *reinterpret_cast<const uint2*>(h + (size_t)ss * HROW + lane * 2);
                float2 f0 = __half22float2(*reinterpret_cast<__half2*>(&u.x));
                float2 f1 = __half22float2(*reinterpret_cast<__half2*>(&u.y));
                a0 += f0.x; a1 += f0.y; a2 += f1.x; a3 += f1.y;
            }
        }
    }
    if (act) {
        uint2 o = make_uint2(hpack(di * a0, di * a1), hpack(di * a2, di * a3));
        *reinterpret_cast<uint2*>(Pout + (size_t)warp * HROW + lane * 2) = o;
    }
}

// ---------------- mma.sync f16 GEMM (HMMA path, portable PTX) ----------------
__device__ __forceinline__ void mma16816(float acc[4], const uint32_t a[4],
                                         uint32_t b0, uint32_t b1) {
    asm volatile(
        "mma.sync.aligned.m16n8k16.row.col.f32.f16.f16.f32 "
        "{%0,%1,%2,%3}, {%4,%5,%6,%7}, {%8,%9}, {%0,%1,%2,%3};"
        : "+f"(acc[0]), "+f"(acc[1]), "+f"(acc[2]), "+f"(acc[3])
        : "r"(a[0]), "r"(a[1]), "r"(a[2]), "r"(a[3]), "r"(b0), "r"(b1));
}

// load fp16 a-frags for one kt: 4 LDG.32
__device__ __forceinline__ void load_afrag(const uint32_t* __restrict__ P,
                                           int ra, int rb, int M, int kt, int lane,
                                           uint32_t ah[4]) {
    int c0 = kt * 8 + (lane & 3);
    ah[0] = (ra < M) ? P[(size_t)ra * HROW + c0]     : 0u;
    ah[1] = (rb < M) ? P[(size_t)rb * HROW + c0]     : 0u;
    ah[2] = (ra < M) ? P[(size_t)ra * HROW + c0 + 4] : 0u;
    ah[3] = (rb < M) ? P[(size_t)rb * HROW + c0 + 4] : 0u;
}

// one K=96 chunk into acc: 2 mmas per (kt,nt)  (A fp16, B = bhi + blo)
__device__ __forceinline__ void gemm_chunk(const __half2* __restrict__ Ph,
                                           const uint4* __restrict__ F,
                                           int row0, int lane, int M,
                                           float acc[12][4]) {
    const uint32_t* P = reinterpret_cast<const uint32_t*>(Ph);
    int r  = lane >> 2;
    int ra = row0 + r, rb = row0 + r + 8;
    #pragma unroll
    for (int kt = 0; kt < 6; kt++) {
        uint32_t ah[4];
        load_afrag(P, ra, rb, M, kt, lane, ah);
        const uint4* fp = F + (size_t)kt * 12 * 32 + lane;
        #pragma unroll
        for (int nt = 0; nt < 12; nt++) {
            uint4 b = fp[nt * 32];
            mma16816(acc[nt], ah, b.x, b.y);   // a * bhi
            mma16816(acc[nt], ah, b.z, b.w);   // a * blo
        }
    }
}

// dual-output GEMM sharing fp16 input A:
//   Lh = half2(relu(A W1 + b1));  G1h = half2( dis * relu(A W2 + b2) )
__global__ void __launch_bounds__(256)
k_dualgemm(const __half2* __restrict__ Ph,
           const uint4* __restrict__ F1, const uint4* __restrict__ F2,
           const float* __restrict__ bias1, const float* __restrict__ bias2,
           __half2* __restrict__ Lh, __half2* __restrict__ G1h, int M) {
    int lane = threadIdx.x & 31, warp = threadIdx.x >> 5;
    int row0 = blockIdx.x * 128 + warp * 16;
    int r  = lane >> 2;
    int cq = (lane & 3) * 2;
    int ra = row0 + r, rb = row0 + r + 8;

    float acc1[12][4], acc2[12][4];
    #pragma unroll
    for (int nt = 0; nt < 12; nt++)
        #pragma unroll
        for (int j = 0; j < 4; j++) { acc1[nt][j] = 0.f; acc2[nt][j] = 0.f; }

    const uint32_t* P = reinterpret_cast<const uint32_t*>(Ph);
    #pragma unroll
    for (int kt = 0; kt < 6; kt++) {
        uint32_t ah[4];
        load_afrag(P, ra, rb, M, kt, lane, ah);
        const uint4* fp1 = F1 + (size_t)kt * 12 * 32 + lane;
        const uint4* fp2 = F2 + (size_t)kt * 12 * 32 + lane;
        #pragma unroll
        for (int nt = 0; nt < 12; nt++) {
            uint4 b1 = fp1[nt * 32];
            mma16816(acc1[nt], ah, b1.x, b1.y);
            mma16816(acc1[nt], ah, b1.z, b1.w);
            uint4 b2 = fp2[nt * 32];
            mma16816(acc2[nt], ah, b2.x, b2.y);
            mma16816(acc2[nt], ah, b2.z, b2.w);
        }
    }

    float da = (ra < M) ? g_dis[ra] : 0.f;
    float db = (rb < M) ? g_dis[rb] : 0.f;
    uint32_t* Lw  = reinterpret_cast<uint32_t*>(Lh);
    uint32_t* G1w = reinterpret_cast<uint32_t*>(G1h);
    #pragma unroll
    for (int nt = 0; nt < 12; nt++) {
        int col = nt * 8 + cq;
        int cpi = col >> 1;
        float2 bb1 = *reinterpret_cast<const float2*>(bias1 + col);
        float2 bb2 = *reinterpret_cast<const float2*>(bias2 + col);
        if (ra < M) {
            Lw [(size_t)ra * HROW + cpi] = hpack(fmaxf(acc1[nt][0] + bb1.x, 0.f),
                                                fmaxf(acc1[nt][1] + bb1.y, 0.f));
            G1w[(size_t)ra * HROW + cpi] = hpack(da * fmaxf(acc2[nt][0] + bb2.x, 0.f),
                                                 da * fmaxf(acc2[nt][1] + bb2.y, 0.f));
        }
        if (rb < M) {
            Lw [(size_t)rb * HROW + cpi] = hpack(fmaxf(acc1[nt][2] + bb1.x, 0.f),
                                                fmaxf(acc1[nt][3] + bb1.y, 0.f));
            G1w[(size_t)rb * HROW + cpi] = hpack(db * fmaxf(acc2[nt][2] + bb2.x, 0.f),
                                                 db * fmaxf(acc2[nt][3] + bb2.y, 0.f));
        }
    }
}

// fused: g2 = relu(Bv Wg2 + b_g2) in registers; out = L Wf_top + g2 Wf_bot + b_fuse
__global__ void __launch_bounds__(256)
k_fuse2(const __half2* __restrict__ Bvh, const __half2* __restrict__ Lh,
        const uint4* __restrict__ Fg2, const uint4* __restrict__ Ftop,
        const uint4* __restrict__ Fbot,
        const float* __restrict__ bias_g2, const float* __restrict__ bias_f,
        float* __restrict__ out, int M) {
    int lane = threadIdx.x & 31, warp = threadIdx.x >> 5;
    int row0 = blockIdx.x * 128 + warp * 16;
    int r  = lane >> 2;
    int cq = (lane & 3) * 2;
    int ra = row0 + r, rb = row0 + r + 8;

    // phase 1: g2 accumulators
    float g2[12][4];
    #pragma unroll
    for (int nt = 0; nt < 12; nt++)
        #pragma unroll
        for (int j = 0; j < 4; j++) g2[nt][j] = 0.f;
    gemm_chunk(Bvh, Fg2, row0, lane, M, g2);
    #pragma unroll
    for (int nt = 0; nt < 12; nt++) {
        int col = nt * 8 + cq;
        float2 bb = *reinterpret_cast<const float2*>(bias_g2 + col);
        g2[nt][0] = fmaxf(g2[nt][0] + bb.x, 0.f);
        g2[nt][1] = fmaxf(g2[nt][1] + bb.y, 0.f);
        g2[nt][2] = fmaxf(g2[nt][2] + bb.x, 0.f);
        g2[nt][3] = fmaxf(g2[nt][3] + bb.y, 0.f);
    }

    // phase 2: out = L @ Wf_top
    float acc[12][4];
    #pragma unroll
    for (int nt = 0; nt < 12; nt++)
        #pragma unroll
        for (int j = 0; j < 4; j++) acc[nt][j] = 0.f;
    gemm_chunk(Lh, Ftop, row0, lane, M, acc);

    // phase 3: out += g2 @ Wf_bot (C-frag of g2 reinterpreted as A-frags, fp16)
    #pragma unroll
    for (int kt = 0; kt < 6; kt++) {
        uint32_t ah[4] = { hpack(g2[2*kt][0],   g2[2*kt][1]),
                           hpack(g2[2*kt][2],   g2[2*kt][3]),
                           hpack(g2[2*kt+1][0], g2[2*kt+1][1]),
                           hpack(g2[2*kt+1][2], g2[2*kt+1][3]) };
        const uint4* fp = Fbot + (size_t)kt * 12 * 32 + lane;
        #pragma unroll
        for (int nt = 0; nt < 12; nt++) {
            uint4 b = fp[nt * 32];
            mma16816(acc[nt], ah, b.x, b.y);
            mma16816(acc[nt], ah, b.z, b.w);
        }
    }

    #pragma unroll
    for (int nt = 0; nt < 12; nt++) {
        int col = nt * 8 + cq;
        float2 bb = *reinterpret_cast<const float2*>(bias_f + col);
        float2 va = make_float2(acc[nt][0] + bb.x, acc[nt][1] + bb.y);
        float2 vb = make_float2(acc[nt][2] + bb.x, acc[nt][3] + bb.y);
        if (ra < M) *reinterpret_cast<float2*>(out + (size_t)ra * FDIM + col) = va;
        if (rb < M) *reinterpret_cast<float2*>(out + (size_t)rb * FDIM + col) = vb;
    }
}

// ---------------- launch ----------------
extern "C" void kernel_launch(void* const* d_in, const int* in_sizes, int n_in,
                              void* d_out, int out_size) {
    const float* x       = (const float*)d_in[0];
    const int*   ei      = (const int*)  d_in[1];
    const float* W_local = (const float*)d_in[2];
    const float* b_local = (const float*)d_in[3];
    const float* W_g1    = (const float*)d_in[4];
    const float* b_g1    = (const float*)d_in[5];
    const float* W_g2    = (const float*)d_in[6];
    const float* b_g2    = (const float*)d_in[7];
    const float* W_fuse  = (const float*)d_in[8];
    const float* b_fuse  = (const float*)d_in[9];
    float* out = (float*)d_out;

    int n = in_sizes[0] / FDIM; if (n > NMAX) n = NMAX;
    int e = in_sizes[1] / 2;    if (e > EMAX) e = EMAX;

    __half2 *pXh, *pG1h, *pAh, *pLh, *pBvh;
    uint4* pF;
    cudaGetSymbolAddress((void**)&pXh,  g_Xh);
    cudaGetSymbolAddress((void**)&pG1h, g_G1h);
    cudaGetSymbolAddress((void**)&pAh,  g_Ah);
    cudaGetSymbolAddress((void**)&pLh,  g_Lh);
    cudaGetSymbolAddress((void**)&pBvh, g_Bvh);
    cudaGetSymbolAddress((void**)&pF,   g_frag);

    const int tb = 256;
    int eq = (e + 3) / 4;
    int prepThreads = (n > 5 * FRAG_PER_IMG) ? n : 5 * FRAG_PER_IMG;
    // prepB also zeroes g_deg — must precede k_fill
    k_prepB<<<(prepThreads + tb - 1) / tb, tb>>>(W_local, W_g1, W_g2, W_fuse, n);
    k_fill <<<(eq + tb - 1) / tb, tb>>>(ei, e);
    // toH computes dis from deg (needs fill done) and prescales x
    k_toH  <<<(n * 24 + tb - 1) / tb, tb>>>(x, n);

    int aggGrid = (n + 7) / 8;
    int gGrid   = (n + 127) / 128;

    // Ah = half(P x)
    k_agg<<<aggGrid, 256>>>(pXh, pAh, n);
    // Lh = half(relu(A Wl + b)); G1h = half(dis * relu(A Wg1 + b))
    k_dualgemm<<<gGrid, 256>>>(pAh, pF + 0 * FRAG_PER_IMG, pF + 1 * FRAG_PER_IMG,
                               b_local, b_g1, pLh, pG1h, n);
    // Bvh = half(P g1)
    k_agg<<<aggGrid, 256>>>(pG1h, pBvh, n);
    // out = L Wf_top + relu(Bv Wg2 + b) Wf_bot + b_fuse
    k_fuse2<<<gGrid, 256>>>(pBvh, pLh,
                            pF + 2 * FRAG_PER_IMG, pF + 3 * FRAG_PER_IMG, pF + 4 * FRAG_PER_IMG,
                            b_g2, b_fuse, out, n);
}